// round 2
// baseline (speedup 1.0000x reference)
#include <cuda_runtime.h>
#include <cstdint>

#define HH 512
#define WW 512
#define NB 16
#define NPIX (HH*WW)

static __device__ float g_d[NB*NPIX];           // chamfer buffer: fwd result, then final dist
static __device__ unsigned char g_bmask[NB*NPIX]; // bit0 = boundary, bit1 = m (fg mask)
static __device__ int g_flags[NB];               // bit0 = has_fg, bit1 = has_boundary
static __device__ float g_mx[NB];                // per-sample max of final dist
static __device__ double g_acc[2 + 3*NB];        // [0]=focal sum, [1]=bnd sum, inter[b], sump[b], sumt[b]

// ---------------------------------------------------------------------------
__global__ void k_init() {
    int i = threadIdx.x;
    if (i < 2 + 3*NB) g_acc[i] = 0.0;
    if (i < NB) g_flags[i] = 0;
}

// ---------------------------------------------------------------------------
// Morphological boundary: dil = maxpool3(m) (pad 0), ero = AND3x3(m) (pad treated as fg)
__global__ void k_boundary(const int* __restrict__ tgt) {
    int b = blockIdx.y;
    int idx = blockIdx.x * blockDim.x + threadIdx.x;   // grid sized exactly to NPIX
    int i = idx >> 9;
    int j = idx & (WW - 1);
    const int* t = tgt + (size_t)b * NPIX;
    int dil = 0, ero = 1;
    #pragma unroll
    for (int di = -1; di <= 1; di++) {
        int ii = i + di;
        bool rin = (unsigned)ii < HH;
        #pragma unroll
        for (int dj = -1; dj <= 1; dj++) {
            int jj = j + dj;
            bool inb = rin && ((unsigned)jj < WW);
            int mv = inb ? (t[ii*WW + jj] > 0) : 0;
            dil |= mv;
            ero &= inb ? mv : 1;
        }
    }
    int mc = t[idx] > 0;
    int bd = dil & (ero ^ 1);
    g_bmask[(size_t)b*NPIX + idx] = (unsigned char)(bd | (mc << 1));
    int fl = mc | (bd << 1);
    fl = __reduce_or_sync(0xffffffffu, fl);
    if ((threadIdx.x & 31) == 0 && fl) atomicOr(&g_flags[b], fl);
}

// ---------------------------------------------------------------------------
// Chamfer DT: one warp per sample; thread t owns 16 pass-local columns.
// Forward pass reads seed bytes, writes g_d; backward pass (reversed coords)
// reads g_d and overwrites with final distances (tracking the max).

__device__ __forceinline__ void load_fwd(int b, int r, int q0, int has_b, float v[16]) {
    const unsigned char* bp = g_bmask + (size_t)b*NPIX + r*WW + q0;
    uint4 u = *reinterpret_cast<const uint4*>(bp);
    unsigned w[4] = {u.x, u.y, u.z, u.w};
    #pragma unroll
    for (int k = 0; k < 16; k++) {
        unsigned by = (w[k >> 2] >> ((k & 3) * 8)) & 0xFFu;
        unsigned seed = has_b ? (by & 1u) : (((by >> 1) & 1u) ^ 1u);
        v[k] = seed ? 0.0f : 1.0e6f;
    }
}

__device__ __forceinline__ void load_bwd(int b, int r, int q0, float v[16]) {
    const float* fp = g_d + (size_t)b*NPIX + (HH-1-r)*WW + (WW-16 - q0);
    float tmp[16];
    #pragma unroll
    for (int c = 0; c < 4; c++) {
        float4 a = *reinterpret_cast<const float4*>(fp + 4*c);
        tmp[4*c] = a.x; tmp[4*c+1] = a.y; tmp[4*c+2] = a.z; tmp[4*c+3] = a.w;
    }
    #pragma unroll
    for (int k = 0; k < 16; k++) v[k] = tmp[15-k];
}

__device__ __forceinline__ void store_fwd(int b, int r, int q0, const float cur[16]) {
    float* fp = g_d + (size_t)b*NPIX + r*WW + q0;
    #pragma unroll
    for (int c = 0; c < 4; c++) {
        *reinterpret_cast<float4*>(fp + 4*c) =
            make_float4(cur[4*c], cur[4*c+1], cur[4*c+2], cur[4*c+3]);
    }
}

__device__ __forceinline__ void store_bwd(int b, int r, int q0, const float cur[16]) {
    float* fp = g_d + (size_t)b*NPIX + (HH-1-r)*WW + (WW-16 - q0);
    #pragma unroll
    for (int c = 0; c < 4; c++) {
        *reinterpret_cast<float4*>(fp + 4*c) =
            make_float4(cur[15-4*c], cur[14-4*c], cur[13-4*c], cur[12-4*c]);
    }
}

template <int PASS>
__device__ void chamfer_pass(int b, int has_b, float* mxout) {
    const float A = 0.955f, Bd = 1.3693f, INF = 1.0e6f;
    const int t = threadIdx.x;
    const int q0 = t * 16;
    float prev[16], aj[16];
    #pragma unroll
    for (int k = 0; k < 16; k++) { prev[k] = INF; aj[k] = A * (float)(q0 + k); }

    float nv[16];
    if (PASS == 1) load_fwd(b, 0, q0, has_b, nv); else load_bwd(b, 0, q0, nv);

    float mx = -1.0f;
    for (int r = 0; r < HH; r++) {
        float v[16];
        #pragma unroll
        for (int k = 0; k < 16; k++) v[k] = nv[k];
        if (r + 1 < HH) {                         // prefetch next row
            if (PASS == 1) load_fwd(b, r+1, q0, has_b, nv); else load_bwd(b, r+1, q0, nv);
        }

        // neighbor prev values across thread boundaries
        float ln = __shfl_up_sync(0xffffffffu, prev[15], 1);
        float rn = __shfl_down_sync(0xffffffffu, prev[0], 1);
        if (t == 0)  ln = INF;
        if (t == 31) rn = INF;

        // m = min(drow, up+A, ul+B, ur+B); s = m - A*j
        float s[16];
        #pragma unroll
        for (int k = 0; k < 16; k++) {
            float ul = ((k > 0)  ? prev[k-1] : ln) + Bd;
            float ur = ((k < 15) ? prev[k+1] : rn) + Bd;
            float m = fminf(fminf(v[k], prev[k] + A), fminf(ul, ur));
            s[k] = m - aj[k];
        }

        // thread total via 4-level tree (short critical path into the warp scan)
        float t8[8];
        #pragma unroll
        for (int k = 0; k < 8; k++) t8[k] = fminf(s[2*k], s[2*k+1]);
        float t4a = fminf(t8[0], t8[1]), t4b = fminf(t8[2], t8[3]);
        float t4c = fminf(t8[4], t8[5]), t4d = fminf(t8[6], t8[7]);
        float tot = fminf(fminf(t4a, t4b), fminf(t4c, t4d));

        // local inclusive prefix-min (independent of the shfl chain; runs in its shadow)
        float run[16];
        run[0] = s[0];
        #pragma unroll
        for (int k = 1; k < 16; k++) run[k] = fminf(run[k-1], s[k]);

        // exclusive min-scan of thread totals across the warp
        float x = __shfl_up_sync(0xffffffffu, tot, 1);
        if (t == 0) x = INF;
        #pragma unroll
        for (int o = 1; o < 32; o <<= 1) {
            float y = __shfl_up_sync(0xffffffffu, x, o);
            if (t >= o) x = fminf(x, y);
        }

        float cur[16];
        #pragma unroll
        for (int k = 0; k < 16; k++) cur[k] = aj[k] + fminf(run[k], x);

        if (PASS == 2) {
            #pragma unroll
            for (int k = 0; k < 16; k++) mx = fmaxf(mx, cur[k]);
            store_bwd(b, r, q0, cur);
        } else {
            store_fwd(b, r, q0, cur);
        }
        #pragma unroll
        for (int k = 0; k < 16; k++) prev[k] = cur[k];
    }

    if (PASS == 2) {
        #pragma unroll
        for (int o = 16; o > 0; o >>= 1) mx = fmaxf(mx, __shfl_xor_sync(0xffffffffu, mx, o));
        *mxout = mx;
    }
}

__global__ void __launch_bounds__(32, 1) k_chamfer() {
    int b = blockIdx.x;
    int has_b = (g_flags[b] >> 1) & 1;
    float mx = 0.0f;
    chamfer_pass<1>(b, has_b, nullptr);
    __threadfence_block();
    __syncwarp();
    chamfer_pass<2>(b, has_b, &mx);
    if (threadIdx.x == 0) g_mx[b] = mx;
}

// ---------------------------------------------------------------------------
// Elementwise losses + per-sample reductions.
__global__ void k_loss(const float* __restrict__ pred, const int* __restrict__ tgt) {
    int b = blockIdx.y;
    int flags = g_flags[b];
    bool has_fg = (flags & 1) != 0;
    float mxv = g_mx[b];
    bool donorm = mxv > 0.0f;
    float inv = 1.0f / fmaxf(mxv, 1e-12f);
    size_t base = (size_t)b * NPIX;

    float fs = 0.f, bs = 0.f, is = 0.f, ps = 0.f, ts = 0.f;
    for (int idx = blockIdx.x * blockDim.x + threadIdx.x; idx < NPIX;
         idx += gridDim.x * blockDim.x) {
        float x  = pred[base + idx];
        float tv = (float)tgt[base + idx];      // target is exactly 0/1
        float ax = fabsf(x);
        float ea = __expf(-ax);
        float den = 1.0f + ea;
        float rr = 1.0f / den;
        float p  = (x >= 0.f) ? rr : ea * rr;    // sigmoid
        float ls = fminf(x, 0.f) - __logf(den);  // log_sigmoid(x)
        float bce = (1.f - tv) * x - ls;         // uses logsig(-x) = ls - x
        float pt  = (tv == 1.f) ? p : 1.f - p;
        float at  = (tv == 1.f) ? 0.25f : 0.75f;
        float omp = 1.f - pt;
        fs += at * omp * omp * bce;

        float d = g_d[base + idx];
        d = donorm ? d * inv : d;
        if (!has_fg) d = 1.0f;
        bs += (tv * (1.f - p) + (1.f - tv) * p) * (1.f + d);

        is += p * tv; ps += p; ts += tv;
    }

    // warp reduce
    #pragma unroll
    for (int o = 16; o > 0; o >>= 1) {
        fs += __shfl_xor_sync(0xffffffffu, fs, o);
        bs += __shfl_xor_sync(0xffffffffu, bs, o);
        is += __shfl_xor_sync(0xffffffffu, is, o);
        ps += __shfl_xor_sync(0xffffffffu, ps, o);
        ts += __shfl_xor_sync(0xffffffffu, ts, o);
    }
    __shared__ float sm[8][5];
    int lane = threadIdx.x & 31, wid = threadIdx.x >> 5;
    if (lane == 0) { sm[wid][0]=fs; sm[wid][1]=bs; sm[wid][2]=is; sm[wid][3]=ps; sm[wid][4]=ts; }
    __syncthreads();
    if (threadIdx.x == 0) {
        float a0=0,a1=0,a2=0,a3=0,a4=0;
        for (int w = 0; w < 8; w++) { a0+=sm[w][0]; a1+=sm[w][1]; a2+=sm[w][2]; a3+=sm[w][3]; a4+=sm[w][4]; }
        atomicAdd(&g_acc[0], (double)a0);
        atomicAdd(&g_acc[1], (double)a1);
        atomicAdd(&g_acc[2 + b],        (double)a2);
        atomicAdd(&g_acc[2 + NB + b],   (double)a3);
        atomicAdd(&g_acc[2 + 2*NB + b], (double)a4);
    }
}

// ---------------------------------------------------------------------------
__global__ void k_final(const float* __restrict__ lv, float* __restrict__ out) {
    double N = (double)NB * (double)NPIX;
    double focal = g_acc[0] / N;
    double bnd   = g_acc[1] / N;
    double ds = 0.0, us = 0.0;
    for (int b = 0; b < NB; b++) {
        double inter = g_acc[2 + b];
        double tot   = g_acc[2 + NB + b] + g_acc[2 + 2*NB + b];
        ds += (2.0*inter + 1e-6) / (tot + 1e-6);
        us += (inter + 1e-6) / (tot - inter + 1e-6);
    }
    double dice = 1.0 - ds / NB;
    double iou  = 1.0 - us / NB;
    double l0 = lv[0], l1 = lv[1], l2 = lv[2], l3 = lv[3];
    double total = exp(-l0)*focal + l0 + exp(-l1)*dice + l1
                 + exp(-l2)*bnd + l2 + exp(-l3)*iou + l3;
    out[0] = (float)total;
    out[1] = (float)focal;
    out[2] = (float)dice;
    out[3] = (float)bnd;
    out[4] = (float)iou;
}

// ---------------------------------------------------------------------------
extern "C" void kernel_launch(void* const* d_in, const int* in_sizes, int n_in,
                              void* d_out, int out_size) {
    const float* pred = (const float*)d_in[0];
    const int*   tgt  = (const int*)d_in[1];
    const float* lv   = (const float*)d_in[2];
    float* out = (float*)d_out;

    k_init<<<1, 64>>>();
    k_boundary<<<dim3(NPIX/256, NB), 256>>>(tgt);
    k_chamfer<<<NB, 32>>>();
    k_loss<<<dim3(256, NB), 256>>>(pred, tgt);
    k_final<<<1, 1>>>(lv, out);
}

// round 4
// speedup vs baseline: 1.1149x; 1.1149x over previous
#include <cuda_runtime.h>
#include <cstdint>

#define HH 512
#define WW 512
#define NB 16
#define NPIX (HH*WW)

static __device__ float g_d[NB*NPIX];             // chamfer buffer: fwd result, then final dist
static __device__ unsigned char g_bmask[NB*NPIX]; // bit0 = boundary, bit1 = fg mask
static __device__ int g_flags[NB];                // bit0 = has_fg, bit1 = has_boundary
static __device__ float g_mx[NB];                 // per-sample max of final dist
static __device__ double g_acc[2 + 3*NB];         // focal, bnd, inter[b], sump[b], sumt[b]

// ---------------------------------------------------------------------------
__global__ void k_init() {
    int i = threadIdx.x;
    if (i < 2 + 3*NB) g_acc[i] = 0.0;
    if (i < NB) g_flags[i] = 0;
}

// ---------------------------------------------------------------------------
// Boundary: dil = maxpool3 (pad 0), ero = AND3x3 (pad treated as fg). 4 cols/thread.
__global__ void k_boundary(const int* __restrict__ tgt) {
    int b = blockIdx.y;
    int tix = blockIdx.x * blockDim.x + threadIdx.x;  // 0..65535
    int i  = tix >> 7;          // row
    int c0 = (tix & 127) * 4;   // first of 4 columns
    const int* t = tgt + (size_t)b * NPIX;

    int D[6] = {0,0,0,0,0,0};
    int E[6] = {1,1,1,1,1,1};
    int mc[4];
    #pragma unroll
    for (int di = -1; di <= 1; di++) {
        int ii = i + di;
        if ((unsigned)ii < HH) {
            const int* row = t + ii * WW;
            int4 q = *reinterpret_cast<const int4*>(row + c0);
            int v1 = q.x > 0, v2 = q.y > 0, v3 = q.z > 0, v4 = q.w > 0;
            int dv0, ev0, dv5, ev5;
            if (c0 > 0) { int m = row[c0-1] > 0; dv0 = m; ev0 = m; }
            else        { dv0 = 0; ev0 = 1; }
            if (c0 + 4 < WW) { int m = row[c0+4] > 0; dv5 = m; ev5 = m; }
            else             { dv5 = 0; ev5 = 1; }
            D[0]|=dv0; E[0]&=ev0; D[1]|=v1; E[1]&=v1; D[2]|=v2; E[2]&=v2;
            D[3]|=v3; E[3]&=v3; D[4]|=v4; E[4]&=v4; D[5]|=dv5; E[5]&=ev5;
            if (di == 0) { mc[0]=v1; mc[1]=v2; mc[2]=v3; mc[3]=v4; }
        }
    }
    unsigned pack = 0;
    int anym = 0, anyb = 0;
    #pragma unroll
    for (int k = 0; k < 4; k++) {
        int dil = D[k] | D[k+1] | D[k+2];
        int ero = E[k] & E[k+1] & E[k+2];
        int bd  = dil & (ero ^ 1);
        anym |= mc[k]; anyb |= bd;
        pack |= (unsigned)(bd | (mc[k] << 1)) << (8*k);
    }
    *reinterpret_cast<unsigned*>(g_bmask + (size_t)b*NPIX + i*WW + c0) = pack;
    int fl = anym | (anyb << 1);
    fl = __reduce_or_sync(0xffffffffu, fl);
    if ((threadIdx.x & 31) == 0 && fl) atomicOr(&g_flags[b], fl);
}

// ---------------------------------------------------------------------------
// Chamfer DT: 128 threads / 4 warps per sample; thread owns 4 pass-local cols.
// One __syncthreads per row; cross-warp halo+offset published pre-barrier.

__device__ __forceinline__ void cf_load(int PASS, int b, int r, int q0, int has_b, float v[4]) {
    if (PASS == 1) {
        unsigned u = *reinterpret_cast<const unsigned*>(g_bmask + (size_t)b*NPIX + r*WW + q0);
        #pragma unroll
        for (int k = 0; k < 4; k++) {
            unsigned by = (u >> (8*k)) & 0xFFu;
            unsigned seed = has_b ? (by & 1u) : (((by >> 1) & 1u) ^ 1u);
            v[k] = seed ? 0.0f : 1.0e6f;
        }
    } else {
        const float* fp = g_d + (size_t)b*NPIX + (HH-1-r)*WW + (WW-4 - q0);
        float4 a = *reinterpret_cast<const float4*>(fp);
        v[0] = a.w; v[1] = a.z; v[2] = a.y; v[3] = a.x;
    }
}

template <int PASS>
__device__ void chamfer_pass(int b, int has_b, float* mxout,
                             volatile float (*sm_tot)[4], volatile float (*sm_lb)[4],
                             volatile float (*sm_rb)[4]) {
    const float A = 0.955f, Bd = 1.3693f, INF = 1.0e6f;
    const int t = threadIdx.x;
    const int lane = t & 31, w = t >> 5;
    const int q0 = 4 * t;
    const float aj0 = A * (float)q0,       aj1 = A * (float)(q0+1);
    const float aj2 = A * (float)(q0+2),   aj3 = A * (float)(q0+3);
    const float ajL = A * (float)(q0-1),   ajR = A * (float)(q0+4);

    float p0 = INF, p1 = INF, p2 = INF, p3 = INF;  // prev row cur
    float hl = INF, hr = INF;                       // halo prev values
    float nv[4];
    cf_load(PASS, b, 0, q0, has_b, nv);

    float mx = -1.0f;
    for (int r = 0; r < HH; r++) {
        float v0 = nv[0], v1 = nv[1], v2 = nv[2], v3 = nv[3];
        if (r + 1 < HH) cf_load(PASS, b, r+1, q0, has_b, nv);   // prefetch

        // s = min(drow, up+A, ul+B, ur+B) - A*j
        float s0 = fminf(fminf(v0, p0 + A), fminf(hl + Bd, p1 + Bd)) - aj0;
        float s1 = fminf(fminf(v1, p1 + A), fminf(p0 + Bd, p2 + Bd)) - aj1;
        float s2 = fminf(fminf(v2, p2 + A), fminf(p1 + Bd, p3 + Bd)) - aj2;
        float s3 = fminf(fminf(v3, p3 + A), fminf(p2 + Bd, hr + Bd)) - aj3;

        float run1 = fminf(s0, s1);
        float run2 = fminf(run1, s2);
        float run3 = fminf(run2, s3);
        float tot  = fminf(run1, fminf(s2, s3));   // depth-2, == run3

        // exclusive in-warp min-scan of tot (chain A)
        float x = __shfl_up_sync(0xffffffffu, tot, 1);
        if (lane == 0) x = INF;
        #pragma unroll
        for (int o = 1; o < 32; o <<= 1) {
            float y = __shfl_up_sync(0xffffffffu, x, o);
            if (lane >= o) x = fminf(x, y);
        }
        // warp total via butterfly (chain B, overlaps chain A)
        float bt = tot;
        #pragma unroll
        for (int o = 16; o > 0; o >>= 1) bt = fminf(bt, __shfl_xor_sync(0xffffffffu, bt, o));

        int par = r & 1;
        if (lane == 0)  { sm_tot[par][w] = bt; sm_rb[par][w] = s0; }
        if (lane == 31) { sm_lb[par][w] = fminf(run3, x); }
        __syncthreads();

        float t0s = sm_tot[par][0], t1s = sm_tot[par][1], t2s = sm_tot[par][2];
        float offw = INF;
        if (w > 0) offw = t0s;
        if (w > 1) offw = fminf(offw, t1s);
        if (w > 2) offw = fminf(offw, t2s);
        float xf = fminf(x, offw);

        float c0 = aj0 + fminf(s0,  xf);
        float c1 = aj1 + fminf(run1, xf);
        float c2 = aj2 + fminf(run2, xf);
        float c3 = aj3 + fminf(run3, xf);

        if (PASS == 2) {
            mx = fmaxf(fmaxf(mx, fmaxf(c0, c1)), fmaxf(c2, c3));
            float* fp = g_d + (size_t)b*NPIX + (HH-1-r)*WW + (WW-4 - q0);
            *reinterpret_cast<float4*>(fp) = make_float4(c3, c2, c1, c0);
        } else {
            float* fp = g_d + (size_t)b*NPIX + r*WW + q0;
            *reinterpret_cast<float4*>(fp) = make_float4(c0, c1, c2, c3);
        }

        // halo cur values for next row
        float nhl = __shfl_up_sync(0xffffffffu, c3, 1);
        float nhr = __shfl_down_sync(0xffffffffu, c0, 1);
        if (lane == 0) {
            if (w == 0) nhl = INF;
            else {
                float offm = INF;                 // totals p < w-1
                if (w - 1 > 0) offm = t0s;
                if (w - 1 > 1) offm = fminf(offm, t1s);
                nhl = ajL + fminf(sm_lb[par][w-1], offm);
            }
        }
        if (lane == 31) {
            if (w == 3) nhr = INF;
            else {
                float offp = t0s;                 // totals p <= w
                if (w >= 1) offp = fminf(offp, t1s);
                if (w >= 2) offp = fminf(offp, t2s);
                nhr = ajR + fminf(sm_rb[par][w+1], offp);
            }
        }
        hl = nhl; hr = nhr;
        p0 = c0; p1 = c1; p2 = c2; p3 = c3;
    }

    if (PASS == 2) {
        #pragma unroll
        for (int o = 16; o > 0; o >>= 1) mx = fmaxf(mx, __shfl_xor_sync(0xffffffffu, mx, o));
        if (lane == 0) ((volatile float*)mxout)[w] = mx;
    }
}

__global__ void __launch_bounds__(128, 1) k_chamfer() {
    __shared__ float sm_tot[2][4], sm_lb[2][4], sm_rb[2][4];
    __shared__ float sm_mx[4];
    int b = blockIdx.x;
    int has_b = (g_flags[b] >> 1) & 1;
    chamfer_pass<1>(b, has_b, nullptr,
                    (volatile float(*)[4])sm_tot, (volatile float(*)[4])sm_lb,
                    (volatile float(*)[4])sm_rb);
    __syncthreads();   // pass1 global stores visible to block
    chamfer_pass<2>(b, has_b, sm_mx,
                    (volatile float(*)[4])sm_tot, (volatile float(*)[4])sm_lb,
                    (volatile float(*)[4])sm_rb);
    __syncthreads();
    if (threadIdx.x == 0)
        g_mx[b] = fmaxf(fmaxf(sm_mx[0], sm_mx[1]), fmaxf(sm_mx[2], sm_mx[3]));
}

// ---------------------------------------------------------------------------
// Elementwise losses, vectorized 4-wide.
__device__ __forceinline__ void loss_px(float x, float tv, float d, bool has_fg,
                                        bool donorm, float inv,
                                        float& fs, float& bs, float& is, float& ps, float& ts) {
    float ax = fabsf(x);
    float ea = __expf(-ax);
    float den = 1.0f + ea;
    float rr = 1.0f / den;
    float p  = (x >= 0.f) ? rr : ea * rr;     // sigmoid
    float ls = fminf(x, 0.f) - __logf(den);   // log_sigmoid(x)
    float bce = (1.f - tv) * x - ls;          // logsig(-x) = ls - x
    float pt  = (tv == 1.f) ? p : 1.f - p;
    float at  = (tv == 1.f) ? 0.25f : 0.75f;
    float omp = 1.f - pt;
    fs += at * omp * omp * bce;
    d = donorm ? d * inv : d;
    if (!has_fg) d = 1.0f;
    bs += (tv * (1.f - p) + (1.f - tv) * p) * (1.f + d);
    is += p * tv; ps += p; ts += tv;
}

__global__ void k_loss(const float* __restrict__ pred, const int* __restrict__ tgt) {
    int b = blockIdx.y;
    int flags = g_flags[b];
    bool has_fg = (flags & 1) != 0;
    float mxv = g_mx[b];
    bool donorm = mxv > 0.0f;
    float inv = 1.0f / fmaxf(mxv, 1e-12f);
    size_t base = (size_t)b * NPIX;
    const float4* p4 = reinterpret_cast<const float4*>(pred + base);
    const int4*   t4 = reinterpret_cast<const int4*>(tgt + base);
    const float4* d4 = reinterpret_cast<const float4*>(g_d + base);
    const int n4 = NPIX / 4;

    float fs = 0.f, bs = 0.f, is = 0.f, ps = 0.f, ts = 0.f;
    for (int i = blockIdx.x * blockDim.x + threadIdx.x; i < n4;
         i += gridDim.x * blockDim.x) {
        float4 xv = p4[i]; int4 tq = t4[i]; float4 dv = d4[i];
        loss_px(xv.x, (float)tq.x, dv.x, has_fg, donorm, inv, fs, bs, is, ps, ts);
        loss_px(xv.y, (float)tq.y, dv.y, has_fg, donorm, inv, fs, bs, is, ps, ts);
        loss_px(xv.z, (float)tq.z, dv.z, has_fg, donorm, inv, fs, bs, is, ps, ts);
        loss_px(xv.w, (float)tq.w, dv.w, has_fg, donorm, inv, fs, bs, is, ps, ts);
    }

    #pragma unroll
    for (int o = 16; o > 0; o >>= 1) {
        fs += __shfl_xor_sync(0xffffffffu, fs, o);
        bs += __shfl_xor_sync(0xffffffffu, bs, o);
        is += __shfl_xor_sync(0xffffffffu, is, o);
        ps += __shfl_xor_sync(0xffffffffu, ps, o);
        ts += __shfl_xor_sync(0xffffffffu, ts, o);
    }
    __shared__ float sm[8][5];
    int lane = threadIdx.x & 31, wid = threadIdx.x >> 5;
    if (lane == 0) { sm[wid][0]=fs; sm[wid][1]=bs; sm[wid][2]=is; sm[wid][3]=ps; sm[wid][4]=ts; }
    __syncthreads();
    if (threadIdx.x == 0) {
        float a0=0,a1=0,a2=0,a3=0,a4=0;
        for (int ww = 0; ww < 8; ww++) { a0+=sm[ww][0]; a1+=sm[ww][1]; a2+=sm[ww][2]; a3+=sm[ww][3]; a4+=sm[ww][4]; }
        atomicAdd(&g_acc[0], (double)a0);
        atomicAdd(&g_acc[1], (double)a1);
        atomicAdd(&g_acc[2 + b],        (double)a2);
        atomicAdd(&g_acc[2 + NB + b],   (double)a3);
        atomicAdd(&g_acc[2 + 2*NB + b], (double)a4);
    }
}

// ---------------------------------------------------------------------------
__global__ void k_final(const float* __restrict__ lv, float* __restrict__ out) {
    double N = (double)NB * (double)NPIX;
    double focal = g_acc[0] / N;
    double bnd   = g_acc[1] / N;
    double ds = 0.0, us = 0.0;
    for (int b = 0; b < NB; b++) {
        double inter = g_acc[2 + b];
        double tot   = g_acc[2 + NB + b] + g_acc[2 + 2*NB + b];
        ds += (2.0*inter + 1e-6) / (tot + 1e-6);
        us += (inter + 1e-6) / (tot - inter + 1e-6);
    }
    double dice = 1.0 - ds / NB;
    double iou  = 1.0 - us / NB;
    double l0 = lv[0], l1 = lv[1], l2 = lv[2], l3 = lv[3];
    double total = exp(-l0)*focal + l0 + exp(-l1)*dice + l1
                 + exp(-l2)*bnd + l2 + exp(-l3)*iou + l3;
    out[0] = (float)total;
    out[1] = (float)focal;
    out[2] = (float)dice;
    out[3] = (float)bnd;
    out[4] = (float)iou;
}

// ---------------------------------------------------------------------------
extern "C" void kernel_launch(void* const* d_in, const int* in_sizes, int n_in,
                              void* d_out, int out_size) {
    const float* pred = (const float*)d_in[0];
    const int*   tgt  = (const int*)d_in[1];
    const float* lv   = (const float*)d_in[2];
    float* out = (float*)d_out;

    k_init<<<1, 64>>>();
    k_boundary<<<dim3(256, NB), 256>>>(tgt);
    k_chamfer<<<NB, 128>>>();
    k_loss<<<dim3(64, NB), 256>>>(pred, tgt);
    k_final<<<1, 1>>>(lv, out);
}

// round 5
// speedup vs baseline: 3.8943x; 3.4931x over previous
#include <cuda_runtime.h>
#include <cstdint>

#define HH 512
#define WW 512
#define NB 16
#define NPIX (HH*WW)
#define RB 32
#define MB (HH/RB)   // 16

static __device__ float g_d[NB*NPIX];             // pass1 result, then final dist
static __device__ unsigned char g_bmask[NB*NPIX]; // bit0 = boundary, bit1 = fg mask
static __device__ int g_flags[NB];                // bit0 = has_fg, bit1 = has_boundary
static __device__ int g_mxi[NB];                  // per-sample max dist (float bits)
static __device__ float g_lastrow[NB*MB*WW];      // phase A: local last rows (pass-local)
static __device__ float g_bnd[NB*MB*WW];          // phase B: true block-boundary rows
static __device__ double g_acc[2 + 3*NB];

// ---------------------------------------------------------------------------
__global__ void k_init() {
    int i = threadIdx.x;
    if (i < 2 + 3*NB) g_acc[i] = 0.0;
    if (i < NB) { g_flags[i] = 0; g_mxi[i] = 0; }
}

// ---------------------------------------------------------------------------
__global__ void k_boundary(const int* __restrict__ tgt) {
    int b = blockIdx.y;
    int tix = blockIdx.x * blockDim.x + threadIdx.x;
    int i  = tix >> 7;
    int c0 = (tix & 127) * 4;
    const int* t = tgt + (size_t)b * NPIX;

    int D[6] = {0,0,0,0,0,0};
    int E[6] = {1,1,1,1,1,1};
    int mc[4];
    #pragma unroll
    for (int di = -1; di <= 1; di++) {
        int ii = i + di;
        if ((unsigned)ii < HH) {
            const int* row = t + ii * WW;
            int4 q = *reinterpret_cast<const int4*>(row + c0);
            int v1 = q.x > 0, v2 = q.y > 0, v3 = q.z > 0, v4 = q.w > 0;
            int dv0, ev0, dv5, ev5;
            if (c0 > 0) { int m = row[c0-1] > 0; dv0 = m; ev0 = m; }
            else        { dv0 = 0; ev0 = 1; }
            if (c0 + 4 < WW) { int m = row[c0+4] > 0; dv5 = m; ev5 = m; }
            else             { dv5 = 0; ev5 = 1; }
            D[0]|=dv0; E[0]&=ev0; D[1]|=v1; E[1]&=v1; D[2]|=v2; E[2]&=v2;
            D[3]|=v3; E[3]&=v3; D[4]|=v4; E[4]&=v4; D[5]|=dv5; E[5]&=ev5;
            if (di == 0) { mc[0]=v1; mc[1]=v2; mc[2]=v3; mc[3]=v4; }
        }
    }
    unsigned pack = 0;
    int anym = 0, anyb = 0;
    #pragma unroll
    for (int k = 0; k < 4; k++) {
        int dil = D[k] | D[k+1] | D[k+2];
        int ero = E[k] & E[k+1] & E[k+2];
        int bd  = dil & (ero ^ 1);
        anym |= mc[k]; anyb |= bd;
        pack |= (unsigned)(bd | (mc[k] << 1)) << (8*k);
    }
    *reinterpret_cast<unsigned*>(g_bmask + (size_t)b*NPIX + i*WW + c0) = pack;
    int fl = anym | (anyb << 1);
    fl = __reduce_or_sync(0xffffffffu, fl);
    if ((threadIdx.x & 31) == 0 && fl) atomicOr(&g_flags[b], fl);
}

// ---------------------------------------------------------------------------
// Seed loads in pass-local coordinates.
template<int PASS>
__device__ __forceinline__ void cf_load(int b, int r, int q0, int has_b, float v[4]) {
    if (PASS == 1) {
        unsigned u = *reinterpret_cast<const unsigned*>(g_bmask + (size_t)b*NPIX + r*WW + q0);
        #pragma unroll
        for (int k = 0; k < 4; k++) {
            unsigned by = (u >> (8*k)) & 0xFFu;
            unsigned seed = has_b ? (by & 1u) : (((by >> 1) & 1u) ^ 1u);
            v[k] = seed ? 0.0f : 1.0e6f;
        }
    } else {
        const float* fp = g_d + (size_t)b*NPIX + (HH-1-r)*WW + (WW-4 - q0);
        float4 a = *reinterpret_cast<const float4*>(fp);
        v[0] = a.w; v[1] = a.z; v[2] = a.y; v[3] = a.x;
    }
}

// ---------------------------------------------------------------------------
// Phase A (STOREALL=0): 32 local row-steps from INF; store last row only.
// Phase C (STOREALL=1, LOADBND=1): 32 row-steps from true boundary; store all.
template<int PASS, bool LOADBND, bool STOREALL>
__global__ void __launch_bounds__(128, 1) k_block() {
    __shared__ float sm_tot[2][4], sm_lb[2][4], sm_rb[2][4];
    const float A = 0.955f, Bd = 1.3693f, INF = 1.0e6f;
    int m = blockIdx.x;
    int b = blockIdx.y;
    int has_b = (g_flags[b] >> 1) & 1;
    const int t = threadIdx.x;
    const int lane = t & 31, w = t >> 5;
    const int q0 = 4 * t;
    const float aj0 = A * (float)q0,     aj1 = A * (float)(q0+1);
    const float aj2 = A * (float)(q0+2), aj3 = A * (float)(q0+3);
    const float ajL = A * (float)(q0-1), ajR = A * (float)(q0+4);

    float p0 = INF, p1 = INF, p2 = INF, p3 = INF, hl = INF, hr = INF;
    if (LOADBND && m > 0) {
        const float* br = g_bnd + ((size_t)b*MB + (m-1))*WW;
        float4 pv = *reinterpret_cast<const float4*>(br + q0);
        p0 = pv.x; p1 = pv.y; p2 = pv.z; p3 = pv.w;
        float sl = __shfl_up_sync(0xffffffffu, p3, 1);
        float sr = __shfl_down_sync(0xffffffffu, p0, 1);
        hl = (q0 == 0) ? INF : ((lane == 0) ? br[q0-1] : sl);
        hr = (q0 + 4 >= WW) ? INF : ((lane == 31) ? br[q0+4] : sr);
    }

    float nv[4];
    cf_load<PASS>(b, RB*m, q0, has_b, nv);

    float mx = -1.0f;
    for (int u = 0; u < RB; u++) {
        int r = RB*m + u;
        float v0 = nv[0], v1 = nv[1], v2 = nv[2], v3 = nv[3];
        if (u + 1 < RB) cf_load<PASS>(b, r+1, q0, has_b, nv);

        float s0 = fminf(fminf(v0, p0 + A), fminf(hl + Bd, p1 + Bd)) - aj0;
        float s1 = fminf(fminf(v1, p1 + A), fminf(p0 + Bd, p2 + Bd)) - aj1;
        float s2 = fminf(fminf(v2, p2 + A), fminf(p1 + Bd, p3 + Bd)) - aj2;
        float s3 = fminf(fminf(v3, p3 + A), fminf(p2 + Bd, hr + Bd)) - aj3;

        float run1 = fminf(s0, s1);
        float run2 = fminf(run1, s2);
        float run3 = fminf(run2, s3);
        float tot  = fminf(run1, fminf(s2, s3));

        float x = __shfl_up_sync(0xffffffffu, tot, 1);
        if (lane == 0) x = INF;
        #pragma unroll
        for (int o = 1; o < 32; o <<= 1) {
            float y = __shfl_up_sync(0xffffffffu, x, o);
            if (lane >= o) x = fminf(x, y);
        }
        float bt = tot;
        #pragma unroll
        for (int o = 16; o > 0; o >>= 1) bt = fminf(bt, __shfl_xor_sync(0xffffffffu, bt, o));

        int par = u & 1;
        if (lane == 0)  { sm_tot[par][w] = bt; sm_rb[par][w] = s0; }
        if (lane == 31) { sm_lb[par][w] = fminf(run3, x); }
        __syncthreads();

        float t0s = sm_tot[par][0], t1s = sm_tot[par][1], t2s = sm_tot[par][2];
        float offw = INF;
        if (w > 0) offw = t0s;
        if (w > 1) offw = fminf(offw, t1s);
        if (w > 2) offw = fminf(offw, t2s);
        float xf = fminf(x, offw);

        float c0 = aj0 + fminf(s0,  xf);
        float c1 = aj1 + fminf(run1, xf);
        float c2 = aj2 + fminf(run2, xf);
        float c3 = aj3 + fminf(run3, xf);

        if (STOREALL) {
            if (PASS == 2) {
                mx = fmaxf(fmaxf(mx, fmaxf(c0, c1)), fmaxf(c2, c3));
                float* fp = g_d + (size_t)b*NPIX + (HH-1-r)*WW + (WW-4 - q0);
                *reinterpret_cast<float4*>(fp) = make_float4(c3, c2, c1, c0);
            } else {
                float* fp = g_d + (size_t)b*NPIX + r*WW + q0;
                *reinterpret_cast<float4*>(fp) = make_float4(c0, c1, c2, c3);
            }
        } else if (u == RB - 1) {
            float* fp = g_lastrow + ((size_t)b*MB + m)*WW + q0;
            *reinterpret_cast<float4*>(fp) = make_float4(c0, c1, c2, c3);
        }

        float nhl = __shfl_up_sync(0xffffffffu, c3, 1);
        float nhr = __shfl_down_sync(0xffffffffu, c0, 1);
        if (lane == 0) {
            if (w == 0) nhl = INF;
            else {
                float offm = INF;
                if (w - 1 > 0) offm = t0s;
                if (w - 1 > 1) offm = fminf(offm, t1s);
                nhl = ajL + fminf(sm_lb[par][w-1], offm);
            }
        }
        if (lane == 31) {
            if (w == 3) nhr = INF;
            else {
                float offp = t0s;
                if (w >= 1) offp = fminf(offp, t1s);
                if (w >= 2) offp = fminf(offp, t2s);
                nhr = ajR + fminf(sm_rb[par][w+1], offp);
            }
        }
        hl = nhl; hr = nhr;
        p0 = c0; p1 = c1; p2 = c2; p3 = c3;
    }

    if (PASS == 2 && STOREALL) {
        #pragma unroll
        for (int o = 16; o > 0; o >>= 1) mx = fmaxf(mx, __shfl_xor_sync(0xffffffffu, mx, o));
        if (lane == 0) atomicMax(&g_mxi[b], __float_as_int(mx));  // mx >= 0
    }
}

// ---------------------------------------------------------------------------
// Phase B: serial boundary chain: bnd[m] = min(L[m], bnd[m-1] (x) K_RB).
// Conv with K_RB via: P1 global shifted prefix-min; P2/P3 width-(RB+1)
// window mins (aligned van Herk over 32-col blocks = 8-lane shfl segments).
__global__ void __launch_bounds__(128, 1) k_bnd() {
    __shared__ float s_pm1[WW], s_sz2[WW], s_pz3[WW];
    __shared__ float s_wt[4];
    const float A = 0.955f, Bd = 1.3693f, INF = 1.0e6f;
    const float BA  = Bd - A;
    const float AT  = A  * (float)RB;
    const float BAT = BA * (float)RB;
    int b = blockIdx.x;
    int t = threadIdx.x, lane = t & 31, w = t >> 5, q0 = 4*t, l8 = lane & 7;
    float aj[4], baj[4];
    #pragma unroll
    for (int c = 0; c < 4; c++) { aj[c] = A*(float)(q0+c); baj[c] = BA*(float)(q0+c); }
    const float* Lb = g_lastrow + (size_t)b*MB*WW;
    float* Bb = g_bnd + (size_t)b*MB*WW;

    float4 lv = *reinterpret_cast<const float4*>(Lb + q0);
    float b0 = lv.x, b1 = lv.y, b2 = lv.z, b3 = lv.w;
    *reinterpret_cast<float4*>(Bb + q0) = lv;

    for (int m = 1; m < MB - 1; m++) {   // bnd[1..14]; bnd[15] unused
        float4 lnx = *reinterpret_cast<const float4*>(Lb + m*WW + q0);

        float z1[4], z2[4], z3[4];
        z1[0]=b0-aj[0]; z1[1]=b1-aj[1]; z1[2]=b2-aj[2]; z1[3]=b3-aj[3];
        z2[0]=b0-baj[0]; z2[1]=b1-baj[1]; z2[2]=b2-baj[2]; z2[3]=b3-baj[3];
        z3[0]=b0+baj[0]; z3[1]=b1+baj[1]; z3[2]=b2+baj[2]; z3[3]=b3+baj[3];

        // z1: global inclusive prefix-min
        float a1[4];
        a1[0]=z1[0]; a1[1]=fminf(a1[0],z1[1]); a1[2]=fminf(a1[1],z1[2]); a1[3]=fminf(a1[2],z1[3]);
        float x = __shfl_up_sync(0xffffffffu, a1[3], 1);
        if (lane == 0) x = INF;
        #pragma unroll
        for (int o = 1; o < 32; o <<= 1) {
            float y = __shfl_up_sync(0xffffffffu, x, o);
            if (lane >= o) x = fminf(x, y);
        }
        float bt = a1[3];
        #pragma unroll
        for (int o = 16; o > 0; o >>= 1) bt = fminf(bt, __shfl_xor_sync(0xffffffffu, bt, o));
        if (lane == 0) s_wt[w] = bt;

        // z2: own prefix + own suffix; 8-lane segmented excl prefix/suffix
        float a2[4], s2[4];
        a2[0]=z2[0]; a2[1]=fminf(a2[0],z2[1]); a2[2]=fminf(a2[1],z2[2]); a2[3]=fminf(a2[2],z2[3]);
        s2[3]=z2[3]; s2[2]=fminf(s2[3],z2[2]); s2[1]=fminf(s2[2],z2[1]); s2[0]=fminf(s2[1],z2[0]);
        float e2 = __shfl_up_sync(0xffffffffu, a2[3], 1, 8);
        if (l8 == 0) e2 = INF;
        #pragma unroll
        for (int o = 1; o < 8; o <<= 1) {
            float y = __shfl_up_sync(0xffffffffu, e2, o, 8);
            if (l8 >= o) e2 = fminf(e2, y);
        }
        float f2 = __shfl_down_sync(0xffffffffu, s2[0], 1, 8);
        if (l8 == 7) f2 = INF;
        #pragma unroll
        for (int o = 1; o < 8; o <<= 1) {
            float y = __shfl_down_sync(0xffffffffu, f2, o, 8);
            if (l8 + o < 8) f2 = fminf(f2, y);
        }
        // z3: same
        float a3[4], s3[4];
        a3[0]=z3[0]; a3[1]=fminf(a3[0],z3[1]); a3[2]=fminf(a3[1],z3[2]); a3[3]=fminf(a3[2],z3[3]);
        s3[3]=z3[3]; s3[2]=fminf(s3[3],z3[2]); s3[1]=fminf(s3[2],z3[1]); s3[0]=fminf(s3[1],z3[0]);
        float e3 = __shfl_up_sync(0xffffffffu, a3[3], 1, 8);
        if (l8 == 0) e3 = INF;
        #pragma unroll
        for (int o = 1; o < 8; o <<= 1) {
            float y = __shfl_up_sync(0xffffffffu, e3, o, 8);
            if (l8 >= o) e3 = fminf(e3, y);
        }
        float f3 = __shfl_down_sync(0xffffffffu, s3[0], 1, 8);
        if (l8 == 7) f3 = INF;
        #pragma unroll
        for (int o = 1; o < 8; o <<= 1) {
            float y = __shfl_down_sync(0xffffffffu, f3, o, 8);
            if (l8 + o < 8) f3 = fminf(f3, y);
        }

        __syncthreads();   // bar1: warp totals visible
        float t0s = s_wt[0], t1s = s_wt[1], t2s = s_wt[2];
        float offw = INF;
        if (w > 0) offw = t0s;
        if (w > 1) offw = fminf(offw, t1s);
        if (w > 2) offw = fminf(offw, t2s);
        float xg = fminf(x, offw);

        float pm1[4], sz2[4], pz3[4];
        #pragma unroll
        for (int c = 0; c < 4; c++) {
            pm1[c] = fminf(a1[c], xg);      // global prefix-min at col
            sz2[c] = fminf(s2[c], f2);      // in-32-block suffix-min of z2 at col
            pz3[c] = fminf(a3[c], e3);      // in-32-block prefix-min of z3 at col
        }
        *reinterpret_cast<float4*>(s_pm1 + q0) = make_float4(pm1[0],pm1[1],pm1[2],pm1[3]);
        *reinterpret_cast<float4*>(s_sz2 + q0) = make_float4(sz2[0],sz2[1],sz2[2],sz2[3]);
        *reinterpret_cast<float4*>(s_pz3 + q0) = make_float4(pz3[0],pz3[1],pz3[2],pz3[3]);
        __syncthreads();   // bar2

        bool hasL = (q0 >= RB);
        bool hasR = (q0 <= WW - RB - 4);
        float4 pmm = make_float4(INF,INF,INF,INF), szm = pmm, pzm = pmm;
        if (hasL) {
            pmm = *reinterpret_cast<const float4*>(s_pm1 + q0 - RB);
            szm = *reinterpret_cast<const float4*>(s_sz2 + q0 - RB);
        }
        if (hasR) pzm = *reinterpret_cast<const float4*>(s_pz3 + q0 + RB);
        const float* pmp = reinterpret_cast<const float*>(&pmm);
        const float* szp = reinterpret_cast<const float*>(&szm);
        const float* pzp = reinterpret_cast<const float*>(&pzm);
        const float* lnp = reinterpret_cast<const float*>(&lnx);

        float nb[4];
        #pragma unroll
        for (int c = 0; c < 4; c++) {
            float P1v = hasL ? (aj[c] + BAT + pmp[c]) : INF;
            float w2 = fminf(a2[c], e2);
            if (hasL) w2 = fminf(w2, szp[c]);
            float P2v = baj[c] + AT + w2;
            float w3 = fminf(s3[c], f3);
            if (hasR) w3 = fminf(w3, pzp[c]);
            float P3v = AT - baj[c] + w3;
            nb[c] = fminf(fminf(lnp[c], P1v), fminf(P2v, P3v));
        }
        b0 = nb[0]; b1 = nb[1]; b2 = nb[2]; b3 = nb[3];
        *reinterpret_cast<float4*>(Bb + m*WW + q0) = make_float4(b0,b1,b2,b3);
    }
}

// ---------------------------------------------------------------------------
__device__ __forceinline__ void loss_px(float x, float tv, float d, bool has_fg,
                                        bool donorm, float inv,
                                        float& fs, float& bs, float& is, float& ps, float& ts) {
    float ax = fabsf(x);
    float ea = __expf(-ax);
    float den = 1.0f + ea;
    float rr = 1.0f / den;
    float p  = (x >= 0.f) ? rr : ea * rr;
    float ls = fminf(x, 0.f) - __logf(den);
    float bce = (1.f - tv) * x - ls;
    float pt  = (tv == 1.f) ? p : 1.f - p;
    float at  = (tv == 1.f) ? 0.25f : 0.75f;
    float omp = 1.f - pt;
    fs += at * omp * omp * bce;
    d = donorm ? d * inv : d;
    if (!has_fg) d = 1.0f;
    bs += (tv * (1.f - p) + (1.f - tv) * p) * (1.f + d);
    is += p * tv; ps += p; ts += tv;
}

__global__ void k_loss(const float* __restrict__ pred) {
    int b = blockIdx.y;
    int flags = g_flags[b];
    bool has_fg = (flags & 1) != 0;
    float mxv = __int_as_float(g_mxi[b]);
    bool donorm = mxv > 0.0f;
    float inv = 1.0f / fmaxf(mxv, 1e-12f);
    size_t base = (size_t)b * NPIX;
    const float4*   p4 = reinterpret_cast<const float4*>(pred + base);
    const unsigned* m4 = reinterpret_cast<const unsigned*>(g_bmask + base);
    const float4*   d4 = reinterpret_cast<const float4*>(g_d + base);
    const int n4 = NPIX / 4;

    float fs = 0.f, bs = 0.f, is = 0.f, ps = 0.f, ts = 0.f;
    for (int i = blockIdx.x * blockDim.x + threadIdx.x; i < n4;
         i += gridDim.x * blockDim.x) {
        float4 xv = p4[i]; unsigned um = m4[i]; float4 dv = d4[i];
        loss_px(xv.x, (float)((um >> 1)  & 1u), dv.x, has_fg, donorm, inv, fs, bs, is, ps, ts);
        loss_px(xv.y, (float)((um >> 9)  & 1u), dv.y, has_fg, donorm, inv, fs, bs, is, ps, ts);
        loss_px(xv.z, (float)((um >> 17) & 1u), dv.z, has_fg, donorm, inv, fs, bs, is, ps, ts);
        loss_px(xv.w, (float)((um >> 25) & 1u), dv.w, has_fg, donorm, inv, fs, bs, is, ps, ts);
    }

    #pragma unroll
    for (int o = 16; o > 0; o >>= 1) {
        fs += __shfl_xor_sync(0xffffffffu, fs, o);
        bs += __shfl_xor_sync(0xffffffffu, bs, o);
        is += __shfl_xor_sync(0xffffffffu, is, o);
        ps += __shfl_xor_sync(0xffffffffu, ps, o);
        ts += __shfl_xor_sync(0xffffffffu, ts, o);
    }
    __shared__ float sm[8][5];
    int lane = threadIdx.x & 31, wid = threadIdx.x >> 5;
    if (lane == 0) { sm[wid][0]=fs; sm[wid][1]=bs; sm[wid][2]=is; sm[wid][3]=ps; sm[wid][4]=ts; }
    __syncthreads();
    if (threadIdx.x == 0) {
        float a0=0,a1=0,a2=0,a3=0,a4=0;
        for (int ww = 0; ww < 8; ww++) { a0+=sm[ww][0]; a1+=sm[ww][1]; a2+=sm[ww][2]; a3+=sm[ww][3]; a4+=sm[ww][4]; }
        atomicAdd(&g_acc[0], (double)a0);
        atomicAdd(&g_acc[1], (double)a1);
        atomicAdd(&g_acc[2 + b],        (double)a2);
        atomicAdd(&g_acc[2 + NB + b],   (double)a3);
        atomicAdd(&g_acc[2 + 2*NB + b], (double)a4);
    }
}

// ---------------------------------------------------------------------------
__global__ void k_final(const float* __restrict__ lv, float* __restrict__ out) {
    double N = (double)NB * (double)NPIX;
    double focal = g_acc[0] / N;
    double bnd   = g_acc[1] / N;
    double ds = 0.0, us = 0.0;
    for (int b = 0; b < NB; b++) {
        double inter = g_acc[2 + b];
        double tot   = g_acc[2 + NB + b] + g_acc[2 + 2*NB + b];
        ds += (2.0*inter + 1e-6) / (tot + 1e-6);
        us += (inter + 1e-6) / (tot - inter + 1e-6);
    }
    double dice = 1.0 - ds / NB;
    double iou  = 1.0 - us / NB;
    double l0 = lv[0], l1 = lv[1], l2 = lv[2], l3 = lv[3];
    double total = exp(-l0)*focal + l0 + exp(-l1)*dice + l1
                 + exp(-l2)*bnd + l2 + exp(-l3)*iou + l3;
    out[0] = (float)total;
    out[1] = (float)focal;
    out[2] = (float)dice;
    out[3] = (float)bnd;
    out[4] = (float)iou;
}

// ---------------------------------------------------------------------------
extern "C" void kernel_launch(void* const* d_in, const int* in_sizes, int n_in,
                              void* d_out, int out_size) {
    const float* pred = (const float*)d_in[0];
    const float* lv   = (const float*)d_in[2];
    float* out = (float*)d_out;

    k_init<<<1, 64>>>();
    k_boundary<<<dim3(256, NB), 256>>>((const int*)d_in[1]);
    // pass 1
    k_block<1, false, false><<<dim3(MB-1, NB), 128>>>();  // phase A (m=0..14)
    k_bnd<<<NB, 128>>>();                                  // phase B
    k_block<1, true,  true ><<<dim3(MB,   NB), 128>>>();  // phase C
    // pass 2
    k_block<2, false, false><<<dim3(MB-1, NB), 128>>>();
    k_bnd<<<NB, 128>>>();
    k_block<2, true,  true ><<<dim3(MB,   NB), 128>>>();
    k_loss<<<dim3(64, NB), 256>>>(pred);
    k_final<<<1, 1>>>(lv, out);
}

// round 6
// speedup vs baseline: 4.2800x; 1.0990x over previous
#include <cuda_runtime.h>
#include <cstdint>
#include <math.h>

#define HH 512
#define WW 512
#define NB 16
#define NPIX (HH*WW)
#define RB 16
#define MB (HH/RB)           // 32
#define NPAIR ((MB-2)*(MB-1)/2)   // 465
#define FULL 0xffffffffu

static __device__ float g_d[NB*NPIX];             // pass1 result, then final dist
static __device__ unsigned char g_bmask[NB*NPIX]; // bit0 = boundary, bit1 = fg mask
static __device__ int g_flags[NB];                // bit0 = has_fg, bit1 = has_boundary
static __device__ int g_mxi[NB];                  // per-sample max dist (float bits)
static __device__ float g_lastrow[NB*MB*WW];      // phase A: local last rows
static __device__ float g_bnd[NB*MB*WW];          // phase B result (atomicMin'd)
static __device__ double g_acc[2 + 3*NB];

// ---------------------------------------------------------------------------
__global__ void k_boundary(const int* __restrict__ tgt) {
    int b = blockIdx.y;
    int tix = blockIdx.x * blockDim.x + threadIdx.x;
    int i  = tix >> 7;
    int c0 = (tix & 127) * 4;
    const int* t = tgt + (size_t)b * NPIX;

    int D[6] = {0,0,0,0,0,0};
    int E[6] = {1,1,1,1,1,1};
    int mc[4];
    #pragma unroll
    for (int di = -1; di <= 1; di++) {
        int ii = i + di;
        if ((unsigned)ii < HH) {
            const int* row = t + ii * WW;
            int4 q = *reinterpret_cast<const int4*>(row + c0);
            int v1 = q.x > 0, v2 = q.y > 0, v3 = q.z > 0, v4 = q.w > 0;
            int dv0, ev0, dv5, ev5;
            if (c0 > 0) { int m = row[c0-1] > 0; dv0 = m; ev0 = m; }
            else        { dv0 = 0; ev0 = 1; }
            if (c0 + 4 < WW) { int m = row[c0+4] > 0; dv5 = m; ev5 = m; }
            else             { dv5 = 0; ev5 = 1; }
            D[0]|=dv0; E[0]&=ev0; D[1]|=v1; E[1]&=v1; D[2]|=v2; E[2]&=v2;
            D[3]|=v3; E[3]&=v3; D[4]|=v4; E[4]&=v4; D[5]|=dv5; E[5]&=ev5;
            if (di == 0) { mc[0]=v1; mc[1]=v2; mc[2]=v3; mc[3]=v4; }
        }
    }
    unsigned pack = 0;
    int anym = 0, anyb = 0;
    #pragma unroll
    for (int k = 0; k < 4; k++) {
        int dil = D[k] | D[k+1] | D[k+2];
        int ero = E[k] & E[k+1] & E[k+2];
        int bd  = dil & (ero ^ 1);
        anym |= mc[k]; anyb |= bd;
        pack |= (unsigned)(bd | (mc[k] << 1)) << (8*k);
    }
    *reinterpret_cast<unsigned*>(g_bmask + (size_t)b*NPIX + i*WW + c0) = pack;
    int fl = anym | (anyb << 1);
    fl = __reduce_or_sync(FULL, fl);
    if ((threadIdx.x & 31) == 0 && fl) atomicOr(&g_flags[b], fl);
}

// ---------------------------------------------------------------------------
template<int PASS>
__device__ __forceinline__ void cf_load(int b, int r, int q0, int has_b, float v[4]) {
    if (PASS == 1) {
        unsigned u = *reinterpret_cast<const unsigned*>(g_bmask + (size_t)b*NPIX + r*WW + q0);
        #pragma unroll
        for (int k = 0; k < 4; k++) {
            unsigned by = (u >> (8*k)) & 0xFFu;
            unsigned seed = has_b ? (by & 1u) : (((by >> 1) & 1u) ^ 1u);
            v[k] = seed ? 0.0f : 1.0e6f;
        }
    } else {
        const float* fp = g_d + (size_t)b*NPIX + (HH-1-r)*WW + (WW-4 - q0);
        float4 a = *reinterpret_cast<const float4*>(fp);
        v[0] = a.w; v[1] = a.z; v[2] = a.y; v[3] = a.x;
    }
}

// ---------------------------------------------------------------------------
// Phase A (STOREALL=0): RB local row-steps from INF; store last row to
//   g_lastrow AND g_bnd (init for atomicMin).
// Phase C (STOREALL=1, LOADBND=1): RB row-steps from true boundary; store all.
template<int PASS, bool LOADBND, bool STOREALL>
__global__ void __launch_bounds__(128, 1) k_block() {
    __shared__ float sm_tot[2][4], sm_lb[2][4], sm_rb[2][4];
    const float A = 0.955f, Bd = 1.3693f, INF = 1.0e6f;
    int m = blockIdx.x;
    int b = blockIdx.y;
    int has_b = (g_flags[b] >> 1) & 1;
    const int t = threadIdx.x;
    const int lane = t & 31, w = t >> 5;
    const int q0 = 4 * t;
    const float aj0 = A * (float)q0,     aj1 = A * (float)(q0+1);
    const float aj2 = A * (float)(q0+2), aj3 = A * (float)(q0+3);
    const float ajL = A * (float)(q0-1), ajR = A * (float)(q0+4);

    float p0 = INF, p1 = INF, p2 = INF, p3 = INF, hl = INF, hr = INF;
    if (LOADBND && m > 0) {
        const float* br = g_bnd + ((size_t)b*MB + (m-1))*WW;
        float4 pv = *reinterpret_cast<const float4*>(br + q0);
        p0 = pv.x; p1 = pv.y; p2 = pv.z; p3 = pv.w;
        float sl = __shfl_up_sync(FULL, p3, 1);
        float sr = __shfl_down_sync(FULL, p0, 1);
        hl = (q0 == 0) ? INF : ((lane == 0) ? br[q0-1] : sl);
        hr = (q0 + 4 >= WW) ? INF : ((lane == 31) ? br[q0+4] : sr);
    }

    float nv[4], nv2[4];
    cf_load<PASS>(b, RB*m, q0, has_b, nv);
    cf_load<PASS>(b, RB*m + 1, q0, has_b, nv2);

    float mx = -1.0f;
    for (int u = 0; u < RB; u++) {
        int r = RB*m + u;
        float v0 = nv[0], v1 = nv[1], v2 = nv[2], v3 = nv[3];
        #pragma unroll
        for (int k = 0; k < 4; k++) nv[k] = nv2[k];
        if (u + 2 < RB) cf_load<PASS>(b, r+2, q0, has_b, nv2);

        float s0 = fminf(fminf(v0, p0 + A), fminf(hl + Bd, p1 + Bd)) - aj0;
        float s1 = fminf(fminf(v1, p1 + A), fminf(p0 + Bd, p2 + Bd)) - aj1;
        float s2 = fminf(fminf(v2, p2 + A), fminf(p1 + Bd, p3 + Bd)) - aj2;
        float s3 = fminf(fminf(v3, p3 + A), fminf(p2 + Bd, hr + Bd)) - aj3;

        float run1 = fminf(s0, s1);
        float run2 = fminf(run1, s2);
        float run3 = fminf(run2, s3);
        float tot  = fminf(run1, fminf(s2, s3));

        // exclusive in-warp min-scan (clamp trick: out-of-range shfl_up = own)
        float x = __shfl_up_sync(FULL, tot, 1);
        if (lane == 0) x = INF;
        #pragma unroll
        for (int o = 1; o < 32; o <<= 1)
            x = fminf(x, __shfl_up_sync(FULL, x, o));
        float bt = tot;
        #pragma unroll
        for (int o = 16; o > 0; o >>= 1) bt = fminf(bt, __shfl_xor_sync(FULL, bt, o));

        int par = u & 1;
        if (lane == 0)  { sm_tot[par][w] = bt; sm_rb[par][w] = s0; }
        if (lane == 31) { sm_lb[par][w] = fminf(run3, x); }
        __syncthreads();

        float t0s = sm_tot[par][0], t1s = sm_tot[par][1], t2s = sm_tot[par][2];
        float offw = INF;
        if (w > 0) offw = t0s;
        if (w > 1) offw = fminf(offw, t1s);
        if (w > 2) offw = fminf(offw, t2s);
        float xf = fminf(x, offw);

        float c0 = aj0 + fminf(s0,  xf);
        float c1 = aj1 + fminf(run1, xf);
        float c2 = aj2 + fminf(run2, xf);
        float c3 = aj3 + fminf(run3, xf);

        if (STOREALL) {
            if (PASS == 2) {
                mx = fmaxf(fmaxf(mx, fmaxf(c0, c1)), fmaxf(c2, c3));
                float* fp = g_d + (size_t)b*NPIX + (HH-1-r)*WW + (WW-4 - q0);
                *reinterpret_cast<float4*>(fp) = make_float4(c3, c2, c1, c0);
            } else {
                float* fp = g_d + (size_t)b*NPIX + r*WW + q0;
                *reinterpret_cast<float4*>(fp) = make_float4(c0, c1, c2, c3);
            }
        } else if (u == RB - 1) {
            float4 val = make_float4(c0, c1, c2, c3);
            *reinterpret_cast<float4*>(g_lastrow + ((size_t)b*MB + m)*WW + q0) = val;
            *reinterpret_cast<float4*>(g_bnd     + ((size_t)b*MB + m)*WW + q0) = val;
        }

        float nhl = __shfl_up_sync(FULL, c3, 1);
        float nhr = __shfl_down_sync(FULL, c0, 1);
        if (lane == 0) {
            if (w == 0) nhl = INF;
            else {
                float offm = INF;
                if (w - 1 > 0) offm = t0s;
                if (w - 1 > 1) offm = fminf(offm, t1s);
                nhl = ajL + fminf(sm_lb[par][w-1], offm);
            }
        }
        if (lane == 31) {
            if (w == 3) nhr = INF;
            else {
                float offp = t0s;
                if (w >= 1) offp = fminf(offp, t1s);
                if (w >= 2) offp = fminf(offp, t2s);
                nhr = ajR + fminf(sm_rb[par][w+1], offp);
            }
        }
        hl = nhl; hr = nhr;
        p0 = c0; p1 = c1; p2 = c2; p3 = c3;
    }

    if (PASS == 2 && STOREALL) {
        #pragma unroll
        for (int o = 16; o > 0; o >>= 1) mx = fmaxf(mx, __shfl_xor_sync(FULL, mx, o));
        if (t == 0) atomicMax(&g_mxi[b], __float_as_int(mx));
    }
}

// ---------------------------------------------------------------------------
// All-pairs phase B: block (m,p) computes L[p] (x) K_{(m-p)*RB}, atomicMin
// into g_bnd[m] (pre-initialized to L[m] by phase A).
// K_t(d) = A*t + (B-A)|d| for |d|<=t; (B-A)*t + A*d for d>t; INF for d<-t.
__global__ void __launch_bounds__(128, 8) k_conv() {
    __shared__ float sp1[512], ss2[512], sp3[512];
    __shared__ float tT1[32], tT2[32], tT3[32];
    __shared__ float aT1[32], aT2p[32], aW2[32], aT3s[32], aW3[32];
    const float A = 0.955f, BA = 1.3693f - 0.955f, INF = 1.0e6f;
    int xid = blockIdx.x, b = blockIdx.y;
    int m = (int)((sqrtf(8.0f*(float)xid + 1.0f) + 1.0f) * 0.5f);
    while (m*(m-1)/2 > xid) m--;
    while ((m+1)*m/2 <= xid) m++;
    int p = xid - m*(m-1)/2;
    int n = m - p;                 // 1..30
    int t = n * RB;
    float At = A * (float)t, BAt = BA * (float)t;

    int tid = threadIdx.x, w = tid >> 5, sub = tid & 3;
    int q0 = 4*tid, sj = q0 >> 4, o = q0 & 15;

    const float* L = g_lastrow + ((size_t)b*MB + p)*WW;
    float4 lv = *reinterpret_cast<const float4*>(L + q0);
    float l[4] = {lv.x, lv.y, lv.z, lv.w};
    float z1[4], z2[4], z3[4];
    #pragma unroll
    for (int c = 0; c < 4; c++) {
        float j = (float)(q0 + c);
        z1[c] = l[c] - A * j;
        z2[c] = l[c] - BA * j;
        z3[c] = l[c] + BA * j;
    }
    // thread-local inclusive prefix (a*) / suffix (s*)
    float a1[4]; a1[0]=z1[0]; a1[1]=fminf(a1[0],z1[1]); a1[2]=fminf(a1[1],z1[2]); a1[3]=fminf(a1[2],z1[3]);
    float a2[4]; a2[0]=z2[0]; a2[1]=fminf(a2[0],z2[1]); a2[2]=fminf(a2[1],z2[2]); a2[3]=fminf(a2[2],z2[3]);
    float s2v[4]; s2v[3]=z2[3]; s2v[2]=fminf(s2v[3],z2[2]); s2v[1]=fminf(s2v[2],z2[1]); s2v[0]=fminf(s2v[1],z2[0]);
    float a3[4]; a3[0]=z3[0]; a3[1]=fminf(a3[0],z3[1]); a3[2]=fminf(a3[1],z3[2]); a3[3]=fminf(a3[2],z3[3]);
    float s3v[4]; s3v[3]=z3[3]; s3v[2]=fminf(s3v[3],z3[2]); s3v[1]=fminf(s3v[2],z3[1]); s3v[0]=fminf(s3v[1],z3[0]);

    // 4-lane segment (16 cols) exclusive prefix of thread totals
    float e1 = __shfl_up_sync(FULL, a1[3], 1, 4); if (sub == 0) e1 = INF;
    e1 = fminf(e1, __shfl_up_sync(FULL, e1, 1, 4));
    e1 = fminf(e1, __shfl_up_sync(FULL, e1, 2, 4));
    float e2 = __shfl_up_sync(FULL, a2[3], 1, 4); if (sub == 0) e2 = INF;
    e2 = fminf(e2, __shfl_up_sync(FULL, e2, 1, 4));
    e2 = fminf(e2, __shfl_up_sync(FULL, e2, 2, 4));
    float e3 = __shfl_up_sync(FULL, a3[3], 1, 4); if (sub == 0) e3 = INF;
    e3 = fminf(e3, __shfl_up_sync(FULL, e3, 1, 4));
    e3 = fminf(e3, __shfl_up_sync(FULL, e3, 2, 4));
    // 4-lane exclusive suffix of thread suffix-totals (z2, z3)
    float f2 = __shfl_down_sync(FULL, s2v[0], 1, 4); if (sub == 3) f2 = INF;
    f2 = fminf(f2, __shfl_down_sync(FULL, f2, 1, 4));
    f2 = fminf(f2, __shfl_down_sync(FULL, f2, 2, 4));
    float f3 = __shfl_down_sync(FULL, s3v[0], 1, 4); if (sub == 3) f3 = INF;
    f3 = fminf(f3, __shfl_down_sync(FULL, f3, 1, 4));
    f3 = fminf(f3, __shfl_down_sync(FULL, f3, 2, 4));

    // segment-inclusive values per column
    float sp1r[4], sp2r[4], ss2r[4], sp3r[4], ss3r[4];
    #pragma unroll
    for (int c = 0; c < 4; c++) {
        sp1r[c] = fminf(a1[c], e1);
        sp2r[c] = fminf(a2[c], e2);
        ss2r[c] = fminf(s2v[c], f2);
        sp3r[c] = fminf(a3[c], e3);
        ss3r[c] = fminf(s3v[c], f3);
    }
    *reinterpret_cast<float4*>(sp1 + q0) = make_float4(sp1r[0], sp1r[1], sp1r[2], sp1r[3]);
    *reinterpret_cast<float4*>(ss2 + q0) = make_float4(ss2r[0], ss2r[1], ss2r[2], ss2r[3]);
    *reinterpret_cast<float4*>(sp3 + q0) = make_float4(sp3r[0], sp3r[1], sp3r[2], sp3r[3]);
    if (sub == 3) {
        tT1[sj] = sp1r[3]; tT2[sj] = sp2r[3]; tT3[sj] = sp3r[3];
    }
    __syncthreads();

    int Lw = n - 1;  // mid-segment window length (may be 0)
    if (w == 0) {    // z1: inclusive prefix-min of totals
        int s = tid;
        float v = tT1[s];
        #pragma unroll
        for (int oo = 1; oo < 32; oo <<= 1) v = fminf(v, __shfl_up_sync(FULL, v, oo));
        aT1[s] = v;
    } else if (w == 1) {  // z2: prefix of totals + backward window of len Lw
        int s = tid & 31;
        float T = tT2[s];
        float v = T;
        #pragma unroll
        for (int oo = 1; oo < 32; oo <<= 1) v = fminf(v, __shfl_up_sync(FULL, v, oo));
        aT2p[s] = v;
        if (Lw >= 1) {
            float M1 = T;
            float M2  = fminf(M1,  __shfl_up_sync(FULL, M1, 1));
            float M4  = fminf(M2,  __shfl_up_sync(FULL, M2, 2));
            float M8  = fminf(M4,  __shfl_up_sync(FULL, M4, 4));
            float M16 = fminf(M8,  __shfl_up_sync(FULL, M8, 8));
            float Mp; int pw;
            if      (Lw >= 16) { Mp = M16; pw = 16; }
            else if (Lw >= 8)  { Mp = M8;  pw = 8; }
            else if (Lw >= 4)  { Mp = M4;  pw = 4; }
            else if (Lw >= 2)  { Mp = M2;  pw = 2; }
            else               { Mp = M1;  pw = 1; }
            aW2[s] = fminf(Mp, __shfl_up_sync(FULL, Mp, Lw - pw));
        }
    } else if (w == 2) {  // z3: suffix of totals + forward window of len Lw
        int s = tid & 31;
        float T = tT3[s];
        float v = T;
        #pragma unroll
        for (int oo = 1; oo < 32; oo <<= 1) v = fminf(v, __shfl_down_sync(FULL, v, oo));
        aT3s[s] = v;
        if (Lw >= 1) {
            float N1 = T;
            float N2  = fminf(N1,  __shfl_down_sync(FULL, N1, 1));
            float N4  = fminf(N2,  __shfl_down_sync(FULL, N2, 2));
            float N8  = fminf(N4,  __shfl_down_sync(FULL, N4, 4));
            float N16 = fminf(N8,  __shfl_down_sync(FULL, N8, 8));
            float Np; int pw;
            if      (Lw >= 16) { Np = N16; pw = 16; }
            else if (Lw >= 8)  { Np = N8;  pw = 8; }
            else if (Lw >= 4)  { Np = N4;  pw = 4; }
            else if (Lw >= 2)  { Np = N2;  pw = 2; }
            else               { Np = N1;  pw = 1; }
            aW3[s] = fminf(Np, __shfl_down_sync(FULL, Np, Lw - pw));
        }
    }
    __syncthreads();

    int* dst = reinterpret_cast<int*>(g_bnd + ((size_t)b*MB + m)*WW + q0);
    int sa = sj - n, sb = sj + n;
    bool hasP1 = (q0 >= t);
    int ja = q0 - t;
    int sa1 = ja >> 4;
    float pT1 = (hasP1 && sa1 > 0) ? aT1[sa1 - 1] : INF;
    float w2mid = (sa >= 0 && Lw >= 1) ? aW2[sj - 1] : INF;
    float gp2t  = (sa < 0 && sj > 0)  ? aT2p[sj - 1] : INF;
    float w3mid = (sb <= 31 && Lw >= 1) ? aW3[sj + 1] : INF;
    float gs3t  = (sb > 31 && sj < 31) ? aT3s[sj + 1] : INF;

    #pragma unroll
    for (int c = 0; c < 4; c++) {
        float jf = (float)(q0 + c);
        float best;
        // P2
        float w2;
        if (sa < 0) w2 = fminf(sp2r[c], gp2t);
        else        w2 = fminf(fminf(ss2[sa*16 + o + c], sp2r[c]), w2mid);
        best = BA * jf + At + w2;
        // P3
        float w3;
        if (sb > 31) w3 = fminf(ss3r[c], gs3t);
        else         w3 = fminf(fminf(ss3r[c], sp3[sb*16 + o + c]), w3mid);
        best = fminf(best, At - BA * jf + w3);
        // P1
        if (hasP1) {
            float pm = fminf(sp1[ja + c], pT1);
            best = fminf(best, A * jf + BAt + pm);
        }
        atomicMin(dst + c, __float_as_int(best));
    }
}

// ---------------------------------------------------------------------------
__device__ __forceinline__ void loss_px(float x, float tv, float d, bool has_fg,
                                        bool donorm, float inv,
                                        float& fs, float& bs, float& is, float& ps, float& ts) {
    float ax = fabsf(x);
    float ea = __expf(-ax);
    float den = 1.0f + ea;
    float rr = 1.0f / den;
    float pp = (x >= 0.f) ? rr : ea * rr;
    float ls = fminf(x, 0.f) - __logf(den);
    float bce = (1.f - tv) * x - ls;
    float pt  = (tv == 1.f) ? pp : 1.f - pp;
    float at  = (tv == 1.f) ? 0.25f : 0.75f;
    float omp = 1.f - pt;
    fs += at * omp * omp * bce;
    d = donorm ? d * inv : d;
    if (!has_fg) d = 1.0f;
    bs += (tv * (1.f - pp) + (1.f - tv) * pp) * (1.f + d);
    is += pp * tv; ps += pp; ts += tv;
}

__global__ void k_loss(const float* __restrict__ pred) {
    int b = blockIdx.y;
    int flags = g_flags[b];
    bool has_fg = (flags & 1) != 0;
    float mxv = __int_as_float(g_mxi[b]);
    bool donorm = mxv > 0.0f;
    float inv = 1.0f / fmaxf(mxv, 1e-12f);
    size_t base = (size_t)b * NPIX;
    const float4* p4 = reinterpret_cast<const float4*>(pred + base);
    const uint2*  m2 = reinterpret_cast<const uint2*>(g_bmask + base);
    const float4* d4 = reinterpret_cast<const float4*>(g_d + base);
    const int n8 = NPIX / 8;

    float fs = 0.f, bs = 0.f, is = 0.f, ps = 0.f, ts = 0.f;
    for (int i = blockIdx.x * blockDim.x + threadIdx.x; i < n8;
         i += gridDim.x * blockDim.x) {
        float4 x0 = p4[2*i], x1 = p4[2*i+1];
        uint2  um = m2[i];
        float4 d0 = d4[2*i], d1 = d4[2*i+1];
        loss_px(x0.x, (float)((um.x >> 1)  & 1u), d0.x, has_fg, donorm, inv, fs, bs, is, ps, ts);
        loss_px(x0.y, (float)((um.x >> 9)  & 1u), d0.y, has_fg, donorm, inv, fs, bs, is, ps, ts);
        loss_px(x0.z, (float)((um.x >> 17) & 1u), d0.z, has_fg, donorm, inv, fs, bs, is, ps, ts);
        loss_px(x0.w, (float)((um.x >> 25) & 1u), d0.w, has_fg, donorm, inv, fs, bs, is, ps, ts);
        loss_px(x1.x, (float)((um.y >> 1)  & 1u), d1.x, has_fg, donorm, inv, fs, bs, is, ps, ts);
        loss_px(x1.y, (float)((um.y >> 9)  & 1u), d1.y, has_fg, donorm, inv, fs, bs, is, ps, ts);
        loss_px(x1.z, (float)((um.y >> 17) & 1u), d1.z, has_fg, donorm, inv, fs, bs, is, ps, ts);
        loss_px(x1.w, (float)((um.y >> 25) & 1u), d1.w, has_fg, donorm, inv, fs, bs, is, ps, ts);
    }

    #pragma unroll
    for (int o = 16; o > 0; o >>= 1) {
        fs += __shfl_xor_sync(FULL, fs, o);
        bs += __shfl_xor_sync(FULL, bs, o);
        is += __shfl_xor_sync(FULL, is, o);
        ps += __shfl_xor_sync(FULL, ps, o);
        ts += __shfl_xor_sync(FULL, ts, o);
    }
    __shared__ float sm[8][5];
    int lane = threadIdx.x & 31, wid = threadIdx.x >> 5;
    if (lane == 0) { sm[wid][0]=fs; sm[wid][1]=bs; sm[wid][2]=is; sm[wid][3]=ps; sm[wid][4]=ts; }
    __syncthreads();
    if (threadIdx.x == 0) {
        float a0=0,a1=0,a2=0,a3=0,a4=0;
        for (int ww = 0; ww < 8; ww++) { a0+=sm[ww][0]; a1+=sm[ww][1]; a2+=sm[ww][2]; a3+=sm[ww][3]; a4+=sm[ww][4]; }
        atomicAdd(&g_acc[0], (double)a0);
        atomicAdd(&g_acc[1], (double)a1);
        atomicAdd(&g_acc[2 + b],        (double)a2);
        atomicAdd(&g_acc[2 + NB + b],   (double)a3);
        atomicAdd(&g_acc[2 + 2*NB + b], (double)a4);
    }
}

// ---------------------------------------------------------------------------
// Final combine; then self-reset accumulators for the next invocation
// (globals are zero-initialized at module load, so the first call is clean).
__global__ void k_final(const float* __restrict__ lv, float* __restrict__ out) {
    double N = (double)NB * (double)NPIX;
    double focal = g_acc[0] / N;
    double bnd   = g_acc[1] / N;
    double ds = 0.0, us = 0.0;
    for (int b = 0; b < NB; b++) {
        double inter = g_acc[2 + b];
        double tot   = g_acc[2 + NB + b] + g_acc[2 + 2*NB + b];
        ds += (2.0*inter + 1e-6) / (tot + 1e-6);
        us += (inter + 1e-6) / (tot - inter + 1e-6);
    }
    double dice = 1.0 - ds / NB;
    double iou  = 1.0 - us / NB;
    double l0 = lv[0], l1 = lv[1], l2 = lv[2], l3 = lv[3];
    double total = exp(-l0)*focal + l0 + exp(-l1)*dice + l1
                 + exp(-l2)*bnd + l2 + exp(-l3)*iou + l3;
    out[0] = (float)total;
    out[1] = (float)focal;
    out[2] = (float)dice;
    out[3] = (float)bnd;
    out[4] = (float)iou;
    for (int i = 0; i < 2 + 3*NB; i++) g_acc[i] = 0.0;
    for (int i = 0; i < NB; i++) { g_flags[i] = 0; g_mxi[i] = 0; }
}

// ---------------------------------------------------------------------------
extern "C" void kernel_launch(void* const* d_in, const int* in_sizes, int n_in,
                              void* d_out, int out_size) {
    const float* pred = (const float*)d_in[0];
    const float* lv   = (const float*)d_in[2];
    float* out = (float*)d_out;

    k_boundary<<<dim3(256, NB), 256>>>((const int*)d_in[1]);
    // pass 1
    k_block<1, false, false><<<dim3(MB-1, NB), 128>>>();
    k_conv<<<dim3(NPAIR, NB), 128>>>();
    k_block<1, true,  true ><<<dim3(MB,   NB), 128>>>();
    // pass 2
    k_block<2, false, false><<<dim3(MB-1, NB), 128>>>();
    k_conv<<<dim3(NPAIR, NB), 128>>>();
    k_block<2, true,  true ><<<dim3(MB,   NB), 128>>>();
    k_loss<<<dim3(32, NB), 256>>>(pred);
    k_final<<<1, 1>>>(lv, out);
}

// round 7
// speedup vs baseline: 5.1588x; 1.2053x over previous
#include <cuda_runtime.h>
#include <cstdint>
#include <math.h>

#define HH 512
#define WW 512
#define NB 16
#define NPIX (HH*WW)
#define RB 16
#define MB (HH/RB)                 // 32
#define NPAIR ((MB-2)*(MB-1)/2)    // 465
#define FULL 0xffffffffu

static __device__ float g_d[NB*NPIX];             // pass-1 final dist
static __device__ unsigned char g_bmask[NB*NPIX]; // bit0 boundary, bit1 target
static __device__ int g_mxi[NB];                  // per-sample max dist (float bits)
static __device__ float g_lr1[NB*MB*WW], g_bn1[NB*MB*WW];
static __device__ float g_lr2[NB*MB*WW], g_bn2[NB*MB*WW];
static __device__ double g_acc[2 + 4*NB];         // focal, bndA, bndD[b], inter[b], sump[b], sumt[b]

// ---------------------------------------------------------------------------
// One chamfer row-step: 128 threads / 4 warps, 4 cols/thread. Contains one
// __syncthreads (all threads must call). par must alternate between calls.
__device__ __forceinline__ void row_step(
    float v0, float v1, float v2, float v3,
    float& p0, float& p1, float& p2, float& p3, float& hl, float& hr,
    float aj0, float aj1, float aj2, float aj3, float ajL, float ajR,
    int lane, int w, int par,
    float (*sm_tot)[4], float (*sm_lb)[4], float (*sm_rb)[4])
{
    const float A = 0.955f, Bd = 1.3693f, INF = 1.0e6f;
    float s0 = fminf(fminf(v0, p0 + A), fminf(hl + Bd, p1 + Bd)) - aj0;
    float s1 = fminf(fminf(v1, p1 + A), fminf(p0 + Bd, p2 + Bd)) - aj1;
    float s2 = fminf(fminf(v2, p2 + A), fminf(p1 + Bd, p3 + Bd)) - aj2;
    float s3 = fminf(fminf(v3, p3 + A), fminf(p2 + Bd, hr + Bd)) - aj3;

    float run1 = fminf(s0, s1);
    float run2 = fminf(run1, s2);
    float run3 = fminf(run2, s3);
    float tot  = fminf(run1, fminf(s2, s3));

    float x = __shfl_up_sync(FULL, tot, 1);
    if (lane == 0) x = INF;
    #pragma unroll
    for (int o = 1; o < 32; o <<= 1)
        x = fminf(x, __shfl_up_sync(FULL, x, o));
    float bt = tot;
    #pragma unroll
    for (int o = 16; o > 0; o >>= 1) bt = fminf(bt, __shfl_xor_sync(FULL, bt, o));

    if (lane == 0)  { sm_tot[par][w] = bt; sm_rb[par][w] = s0; }
    if (lane == 31) { sm_lb[par][w] = fminf(run3, x); }
    __syncthreads();

    float t0s = sm_tot[par][0], t1s = sm_tot[par][1], t2s = sm_tot[par][2];
    float offw = INF;
    if (w > 0) offw = t0s;
    if (w > 1) offw = fminf(offw, t1s);
    if (w > 2) offw = fminf(offw, t2s);
    float xf = fminf(x, offw);

    float c0 = aj0 + fminf(s0,  xf);
    float c1 = aj1 + fminf(run1, xf);
    float c2 = aj2 + fminf(run2, xf);
    float c3 = aj3 + fminf(run3, xf);

    float nhl = __shfl_up_sync(FULL, c3, 1);
    float nhr = __shfl_down_sync(FULL, c0, 1);
    if (lane == 0) {
        if (w == 0) nhl = INF;
        else {
            float offm = INF;
            if (w - 1 > 0) offm = t0s;
            if (w - 1 > 1) offm = fminf(offm, t1s);
            nhl = ajL + fminf(sm_lb[par][w-1], offm);
        }
    }
    if (lane == 31) {
        if (w == 3) nhr = INF;
        else {
            float offp = t0s;
            if (w >= 1) offp = fminf(offp, t1s);
            if (w >= 2) offp = fminf(offp, t2s);
            nhr = ajR + fminf(sm_rb[par][w+1], offp);
        }
    }
    hl = nhl; hr = nhr;
    p0 = c0; p1 = c1; p2 = c2; p3 = c3;
}

// Load boundary-row init (prev + halos) from a bnd buffer.
__device__ __forceinline__ void load_init(const float* br, int q0, int lane,
                                          float& p0, float& p1, float& p2, float& p3,
                                          float& hl, float& hr)
{
    const float INF = 1.0e6f;
    float4 pv = *reinterpret_cast<const float4*>(br + q0);
    p0 = pv.x; p1 = pv.y; p2 = pv.z; p3 = pv.w;
    float sl = __shfl_up_sync(FULL, p3, 1);
    float sr = __shfl_down_sync(FULL, p0, 1);
    hl = (q0 == 0) ? INF : ((lane == 0) ? br[q0-1] : sl);
    hr = (q0 + 4 >= WW) ? INF : ((lane == 31) ? br[q0+4] : sr);
}

// ---------------------------------------------------------------------------
// Stage 1: boundary computation (fused) + phase A pass 1.
__global__ void __launch_bounds__(128, 1) kA1(const int* __restrict__ tgt) {
    __shared__ float sm_tot[2][4], sm_lb[2][4], sm_rb[2][4];
    const float A = 0.955f, INF = 1.0e6f;
    int m = blockIdx.x, b = blockIdx.y;
    int t = threadIdx.x, lane = t & 31, w = t >> 5;
    int c0 = 4 * t, R0 = RB * m;
    const int* tb = tgt + (size_t)b * NPIX;

    // ---- boundary (3x3 dil & !ero), rolling 3-row window ----
    unsigned sb[4] = {0, 0, 0, 0};
    int cD0[4] = {0,0,0,0}, cE0[4] = {1,1,1,1};
    int cD1[4] = {0,0,0,0}, cE1[4] = {1,1,1,1};
    int mc1[4] = {0,0,0,0};
    for (int rr = R0 - 1; rr <= R0 + RB; rr++) {
        int cD2[4], cE2[4], mc2[4];
        if ((unsigned)rr < HH) {
            const int* row = tb + rr * WW;
            int4 q = *reinterpret_cast<const int4*>(row + c0);
            int v1 = q.x > 0, v2 = q.y > 0, v3 = q.z > 0, v4 = q.w > 0;
            int hd0, he0, hd5, he5;
            if (c0 > 0)      { int mm = row[c0-1] > 0; hd0 = mm; he0 = mm; }
            else             { hd0 = 0; he0 = 1; }
            if (c0 + 4 < WW) { int mm = row[c0+4] > 0; hd5 = mm; he5 = mm; }
            else             { hd5 = 0; he5 = 1; }
            cD2[0] = hd0|v1|v2; cE2[0] = he0&v1&v2;
            cD2[1] = v1|v2|v3;  cE2[1] = v1&v2&v3;
            cD2[2] = v2|v3|v4;  cE2[2] = v2&v3&v4;
            cD2[3] = v3|v4|hd5; cE2[3] = v3&v4&he5;
            mc2[0] = v1; mc2[1] = v2; mc2[2] = v3; mc2[3] = v4;
        } else {
            #pragma unroll
            for (int c = 0; c < 4; c++) { cD2[c] = 0; cE2[c] = 1; mc2[c] = 0; }
        }
        if (rr > R0) {                    // emit row er = rr-1 in [R0, R0+RB-1]
            int u = rr - 1 - R0;
            unsigned pack = 0;
            #pragma unroll
            for (int c = 0; c < 4; c++) {
                int bd = (cD0[c]|cD1[c]|cD2[c]) & ((cE0[c]&cE1[c]&cE2[c]) ^ 1);
                pack |= (unsigned)(bd | (mc1[c] << 1)) << (8*c);
                sb[c] |= (unsigned)bd << u;
            }
            *reinterpret_cast<unsigned*>(g_bmask + (size_t)b*NPIX + (rr-1)*WW + c0) = pack;
        }
        #pragma unroll
        for (int c = 0; c < 4; c++) {
            cD0[c] = cD1[c]; cE0[c] = cE1[c];
            cD1[c] = cD2[c]; cE1[c] = cE2[c];
            mc1[c] = mc2[c];
        }
    }

    // ---- phase A: RB local row-steps from INF, seeds from register bits ----
    const float aj0 = A*(float)c0,     aj1 = A*(float)(c0+1);
    const float aj2 = A*(float)(c0+2), aj3 = A*(float)(c0+3);
    const float ajL = A*(float)(c0-1), ajR = A*(float)(c0+4);
    float p0 = INF, p1 = INF, p2 = INF, p3 = INF, hl = INF, hr = INF;
    for (int u = 0; u < RB; u++) {
        float v0 = ((sb[0] >> u) & 1u) ? 0.0f : INF;
        float v1 = ((sb[1] >> u) & 1u) ? 0.0f : INF;
        float v2 = ((sb[2] >> u) & 1u) ? 0.0f : INF;
        float v3 = ((sb[3] >> u) & 1u) ? 0.0f : INF;
        row_step(v0, v1, v2, v3, p0, p1, p2, p3, hl, hr,
                 aj0, aj1, aj2, aj3, ajL, ajR, lane, w, u & 1,
                 sm_tot, sm_lb, sm_rb);
    }
    float4 val = make_float4(p0, p1, p2, p3);
    *reinterpret_cast<float4*>(g_lr1 + ((size_t)b*MB + m)*WW + c0) = val;
    *reinterpret_cast<float4*>(g_bn1 + ((size_t)b*MB + m)*WW + c0) = val;
}

// ---------------------------------------------------------------------------
// All-pairs boundary conv: block (m,p): L[p] (x) K_{(m-p)*RB} -> atomicMin bnd[m].
template<int P>
__global__ void __launch_bounds__(128, 8) k_conv() {
    __shared__ float sp1[512], ss2[512], sp3[512];
    __shared__ float tT1[32], tT2[32], tT3[32];
    __shared__ float aT1[32], aT2p[32], aW2[32], aT3s[32], aW3[32];
    const float A = 0.955f, BA = 1.3693f - 0.955f, INF = 1.0e6f;
    const float* LR = (P == 1) ? g_lr1 : g_lr2;
    float* BN = (P == 1) ? g_bn1 : g_bn2;
    int xid = blockIdx.x, b = blockIdx.y;
    int m = (int)((sqrtf(8.0f*(float)xid + 1.0f) + 1.0f) * 0.5f);
    while (m*(m-1)/2 > xid) m--;
    while ((m+1)*m/2 <= xid) m++;
    int p = xid - m*(m-1)/2;
    int n = m - p;
    int t = n * RB;
    float At = A * (float)t, BAt = BA * (float)t;

    int tid = threadIdx.x, w = tid >> 5, sub = tid & 3;
    int q0 = 4*tid, sj = q0 >> 4, o = q0 & 15;

    const float* L = LR + ((size_t)b*MB + p)*WW;
    float4 lv = *reinterpret_cast<const float4*>(L + q0);
    float l[4] = {lv.x, lv.y, lv.z, lv.w};
    float z1[4], z2[4], z3[4];
    #pragma unroll
    for (int c = 0; c < 4; c++) {
        float j = (float)(q0 + c);
        z1[c] = l[c] - A * j;
        z2[c] = l[c] - BA * j;
        z3[c] = l[c] + BA * j;
    }
    float a1[4]; a1[0]=z1[0]; a1[1]=fminf(a1[0],z1[1]); a1[2]=fminf(a1[1],z1[2]); a1[3]=fminf(a1[2],z1[3]);
    float a2[4]; a2[0]=z2[0]; a2[1]=fminf(a2[0],z2[1]); a2[2]=fminf(a2[1],z2[2]); a2[3]=fminf(a2[2],z2[3]);
    float s2v[4]; s2v[3]=z2[3]; s2v[2]=fminf(s2v[3],z2[2]); s2v[1]=fminf(s2v[2],z2[1]); s2v[0]=fminf(s2v[1],z2[0]);
    float a3[4]; a3[0]=z3[0]; a3[1]=fminf(a3[0],z3[1]); a3[2]=fminf(a3[1],z3[2]); a3[3]=fminf(a3[2],z3[3]);
    float s3v[4]; s3v[3]=z3[3]; s3v[2]=fminf(s3v[3],z3[2]); s3v[1]=fminf(s3v[2],z3[1]); s3v[0]=fminf(s3v[1],z3[0]);

    float e1 = __shfl_up_sync(FULL, a1[3], 1, 4); if (sub == 0) e1 = INF;
    e1 = fminf(e1, __shfl_up_sync(FULL, e1, 1, 4));
    e1 = fminf(e1, __shfl_up_sync(FULL, e1, 2, 4));
    float e2 = __shfl_up_sync(FULL, a2[3], 1, 4); if (sub == 0) e2 = INF;
    e2 = fminf(e2, __shfl_up_sync(FULL, e2, 1, 4));
    e2 = fminf(e2, __shfl_up_sync(FULL, e2, 2, 4));
    float e3 = __shfl_up_sync(FULL, a3[3], 1, 4); if (sub == 0) e3 = INF;
    e3 = fminf(e3, __shfl_up_sync(FULL, e3, 1, 4));
    e3 = fminf(e3, __shfl_up_sync(FULL, e3, 2, 4));
    float f2 = __shfl_down_sync(FULL, s2v[0], 1, 4); if (sub == 3) f2 = INF;
    f2 = fminf(f2, __shfl_down_sync(FULL, f2, 1, 4));
    f2 = fminf(f2, __shfl_down_sync(FULL, f2, 2, 4));
    float f3 = __shfl_down_sync(FULL, s3v[0], 1, 4); if (sub == 3) f3 = INF;
    f3 = fminf(f3, __shfl_down_sync(FULL, f3, 1, 4));
    f3 = fminf(f3, __shfl_down_sync(FULL, f3, 2, 4));

    float sp1r[4], sp2r[4], ss2r[4], sp3r[4], ss3r[4];
    #pragma unroll
    for (int c = 0; c < 4; c++) {
        sp1r[c] = fminf(a1[c], e1);
        sp2r[c] = fminf(a2[c], e2);
        ss2r[c] = fminf(s2v[c], f2);
        sp3r[c] = fminf(a3[c], e3);
        ss3r[c] = fminf(s3v[c], f3);
    }
    *reinterpret_cast<float4*>(sp1 + q0) = make_float4(sp1r[0], sp1r[1], sp1r[2], sp1r[3]);
    *reinterpret_cast<float4*>(ss2 + q0) = make_float4(ss2r[0], ss2r[1], ss2r[2], ss2r[3]);
    *reinterpret_cast<float4*>(sp3 + q0) = make_float4(sp3r[0], sp3r[1], sp3r[2], sp3r[3]);
    if (sub == 3) { tT1[sj] = sp1r[3]; tT2[sj] = sp2r[3]; tT3[sj] = sp3r[3]; }
    __syncthreads();

    int Lw = n - 1;
    if (w == 0) {
        int s = tid;
        float v = tT1[s];
        #pragma unroll
        for (int oo = 1; oo < 32; oo <<= 1) v = fminf(v, __shfl_up_sync(FULL, v, oo));
        aT1[s] = v;
    } else if (w == 1) {
        int s = tid & 31;
        float T = tT2[s];
        float v = T;
        #pragma unroll
        for (int oo = 1; oo < 32; oo <<= 1) v = fminf(v, __shfl_up_sync(FULL, v, oo));
        aT2p[s] = v;
        if (Lw >= 1) {
            float M1 = T;
            float M2  = fminf(M1,  __shfl_up_sync(FULL, M1, 1));
            float M4  = fminf(M2,  __shfl_up_sync(FULL, M2, 2));
            float M8  = fminf(M4,  __shfl_up_sync(FULL, M4, 4));
            float M16 = fminf(M8,  __shfl_up_sync(FULL, M8, 8));
            float Mp; int pw;
            if      (Lw >= 16) { Mp = M16; pw = 16; }
            else if (Lw >= 8)  { Mp = M8;  pw = 8; }
            else if (Lw >= 4)  { Mp = M4;  pw = 4; }
            else if (Lw >= 2)  { Mp = M2;  pw = 2; }
            else               { Mp = M1;  pw = 1; }
            aW2[s] = fminf(Mp, __shfl_up_sync(FULL, Mp, Lw - pw));
        }
    } else if (w == 2) {
        int s = tid & 31;
        float T = tT3[s];
        float v = T;
        #pragma unroll
        for (int oo = 1; oo < 32; oo <<= 1) v = fminf(v, __shfl_down_sync(FULL, v, oo));
        aT3s[s] = v;
        if (Lw >= 1) {
            float N1 = T;
            float N2  = fminf(N1,  __shfl_down_sync(FULL, N1, 1));
            float N4  = fminf(N2,  __shfl_down_sync(FULL, N2, 2));
            float N8  = fminf(N4,  __shfl_down_sync(FULL, N4, 4));
            float N16 = fminf(N8,  __shfl_down_sync(FULL, N8, 8));
            float Np; int pw;
            if      (Lw >= 16) { Np = N16; pw = 16; }
            else if (Lw >= 8)  { Np = N8;  pw = 8; }
            else if (Lw >= 4)  { Np = N4;  pw = 4; }
            else if (Lw >= 2)  { Np = N2;  pw = 2; }
            else               { Np = N1;  pw = 1; }
            aW3[s] = fminf(Np, __shfl_down_sync(FULL, Np, Lw - pw));
        }
    }
    __syncthreads();

    int* dst = reinterpret_cast<int*>(BN + ((size_t)b*MB + m)*WW + q0);
    int sa = sj - n, sb_ = sj + n;
    float w2mid = (sa >= 0 && Lw >= 1) ? aW2[sj - 1] : INF;
    float gp2t  = (sa < 0 && sj > 0)  ? aT2p[sj - 1] : INF;
    float w3mid = (sb_ <= 31 && Lw >= 1) ? aW3[sj + 1] : INF;
    float gs3t  = (sb_ > 31 && sj < 31) ? aT3s[sj + 1] : INF;

    #pragma unroll
    for (int c = 0; c < 4; c++) {
        float jf = (float)(q0 + c);
        float w2;
        if (sa < 0) w2 = fminf(sp2r[c], gp2t);
        else        w2 = fminf(fminf(ss2[sa*16 + o + c], sp2r[c]), w2mid);
        float best = BA * jf + At + w2;
        float w3;
        if (sb_ > 31) w3 = fminf(ss3r[c], gs3t);
        else          w3 = fminf(fminf(ss3r[c], sp3[sb_*16 + o + c]), w3mid);
        best = fminf(best, At - BA * jf + w3);
        int jt = q0 + c - t;
        if (jt >= 0) {
            int seg = jt >> 4;
            float pm = sp1[jt];
            if (seg > 0) pm = fminf(pm, aT1[seg - 1]);
            best = fminf(best, A * jf + BAt + pm);
        }
        atomicMin(dst + c, __float_as_int(best));
    }
}

// ---------------------------------------------------------------------------
// Stage 3: phase C pass 1 (store g_d + smem) fused with phase A pass 2.
__global__ void __launch_bounds__(128, 1) kC1A2() {
    __shared__ float sm_tot[2][4], sm_lb[2][4], sm_rb[2][4];
    __shared__ float sbuf[RB][WW];
    const float A = 0.955f, INF = 1.0e6f;
    int m = blockIdx.x, b = blockIdx.y;
    int t = threadIdx.x, lane = t & 31, w = t >> 5;
    int q0 = 4 * t;
    const float aj0 = A*(float)q0,     aj1 = A*(float)(q0+1);
    const float aj2 = A*(float)(q0+2), aj3 = A*(float)(q0+3);
    const float ajL = A*(float)(q0-1), ajR = A*(float)(q0+4);

    // ---- C1: seeds from bmask, init from g_bn1[m-1] ----
    float p0 = INF, p1 = INF, p2 = INF, p3 = INF, hl = INF, hr = INF;
    if (m > 0)
        load_init(g_bn1 + ((size_t)b*MB + (m-1))*WW, q0, lane, p0, p1, p2, p3, hl, hr);

    unsigned nv  = *reinterpret_cast<const unsigned*>(g_bmask + (size_t)b*NPIX + (RB*m)*WW + q0);
    unsigned nv2 = *reinterpret_cast<const unsigned*>(g_bmask + (size_t)b*NPIX + (RB*m+1)*WW + q0);
    for (int u = 0; u < RB; u++) {
        unsigned cu = nv; nv = nv2;
        if (u + 2 < RB)
            nv2 = *reinterpret_cast<const unsigned*>(g_bmask + (size_t)b*NPIX + (RB*m+u+2)*WW + q0);
        float v0 = (cu & 1u)         ? 0.0f : INF;
        float v1 = ((cu >> 8) & 1u)  ? 0.0f : INF;
        float v2 = ((cu >> 16) & 1u) ? 0.0f : INF;
        float v3 = ((cu >> 24) & 1u) ? 0.0f : INF;
        row_step(v0, v1, v2, v3, p0, p1, p2, p3, hl, hr,
                 aj0, aj1, aj2, aj3, ajL, ajR, lane, w, u & 1,
                 sm_tot, sm_lb, sm_rb);
        float4 val = make_float4(p0, p1, p2, p3);
        *reinterpret_cast<float4*>(g_d + (size_t)b*NPIX + (RB*m+u)*WW + q0) = val;
        *reinterpret_cast<float4*>(&sbuf[u][q0]) = val;
    }
    __syncthreads();   // sbuf complete for all warps

    // ---- A2 (pass-2 block 31-m): local from INF, v = sbuf reversed ----
    p0 = p1 = p2 = p3 = INF; hl = hr = INF;
    for (int u2 = 0; u2 < RB; u2++) {
        float4 a = *reinterpret_cast<const float4*>(&sbuf[RB-1-u2][WW-4-q0]);
        row_step(a.w, a.z, a.y, a.x, p0, p1, p2, p3, hl, hr,
                 aj0, aj1, aj2, aj3, ajL, ajR, lane, w, u2 & 1,
                 sm_tot, sm_lb, sm_rb);
    }
    float4 val = make_float4(p0, p1, p2, p3);
    *reinterpret_cast<float4*>(g_lr2 + ((size_t)b*MB + (MB-1-m))*WW + q0) = val;
    *reinterpret_cast<float4*>(g_bn2 + ((size_t)b*MB + (MB-1-m))*WW + q0) = val;
}

// ---------------------------------------------------------------------------
__device__ __forceinline__ void loss_px(float x, float tv, float draw,
    float& fs, float& bA, float& bD, float& iS, float& pS, float& tS)
{
    float ax = fabsf(x);
    float ea = __expf(-ax);
    float den = 1.0f + ea;
    float rr = 1.0f / den;
    float pp = (x >= 0.f) ? rr : ea * rr;
    float ls = fminf(x, 0.f) - __logf(den);
    float bce = (1.f - tv) * x - ls;
    float pt  = (tv == 1.f) ? pp : 1.f - pp;
    float at  = (tv == 1.f) ? 0.25f : 0.75f;
    float omp = 1.f - pt;
    fs += at * omp * omp * bce;
    float base = tv * (1.f - pp) + (1.f - tv) * pp;
    bA += base;
    bD += base * draw;
    iS += pp * tv; pS += pp; tS += tv;
}

// Stage 5: phase C pass 2 with inline loss (no dist stores; mx deferred).
__global__ void __launch_bounds__(128, 1) kC2L(const float* __restrict__ pred) {
    __shared__ float sm_tot[2][4], sm_lb[2][4], sm_rb[2][4];
    __shared__ float red[4][6];
    const float A = 0.955f, INF = 1.0e6f;
    int m = blockIdx.x, b = blockIdx.y;
    int t = threadIdx.x, lane = t & 31, w = t >> 5;
    int q0 = 4 * t;
    const float aj0 = A*(float)q0,     aj1 = A*(float)(q0+1);
    const float aj2 = A*(float)(q0+2), aj3 = A*(float)(q0+3);
    const float ajL = A*(float)(q0-1), ajR = A*(float)(q0+4);
    size_t base = (size_t)b * NPIX;

    float p0 = INF, p1 = INF, p2 = INF, p3 = INF, hl = INF, hr = INF;
    if (m > 0)
        load_init(g_bn2 + ((size_t)b*MB + (m-1))*WW, q0, lane, p0, p1, p2, p3, hl, hr);

    // v-input: pass-1 d in pass-2 orientation (reversed)
    const float* vbase = g_d + base;
    float4 nv  = *reinterpret_cast<const float4*>(vbase + (HH-1-RB*m)*WW + (WW-4-q0));
    float4 nv2 = *reinterpret_cast<const float4*>(vbase + (HH-2-RB*m)*WW + (WW-4-q0));

    float fs = 0.f, bA = 0.f, bD = 0.f, iS = 0.f, pS = 0.f, tS = 0.f;
    float mx = -1.0f;
    for (int u = 0; u < RB; u++) {
        int r  = RB*m + u;          // pass-2 row
        int pr = HH - 1 - r;        // pass-1 row
        float4 cu = nv; nv = nv2;
        if (u + 2 < RB)
            nv2 = *reinterpret_cast<const float4*>(vbase + (pr-2)*WW + (WW-4-q0));
        // issue loss inputs early (independent of the scan chain)
        float4 xv = *reinterpret_cast<const float4*>(pred + base + pr*WW + (WW-4-q0));
        unsigned um = *reinterpret_cast<const unsigned*>(g_bmask + base + pr*WW + (WW-4-q0));

        row_step(cu.w, cu.z, cu.y, cu.x, p0, p1, p2, p3, hl, hr,
                 aj0, aj1, aj2, aj3, ajL, ajR, lane, w, u & 1,
                 sm_tot, sm_lb, sm_rb);
        mx = fmaxf(fmaxf(mx, fmaxf(p0, p1)), fmaxf(p2, p3));

        // pass-1 col (WW-4-q0)+i pairs dist c[3-i] = {p3,p2,p1,p0}[...]
        loss_px(xv.x, (float)((um >> 1)  & 1u), p3, fs, bA, bD, iS, pS, tS);
        loss_px(xv.y, (float)((um >> 9)  & 1u), p2, fs, bA, bD, iS, pS, tS);
        loss_px(xv.z, (float)((um >> 17) & 1u), p1, fs, bA, bD, iS, pS, tS);
        loss_px(xv.w, (float)((um >> 25) & 1u), p0, fs, bA, bD, iS, pS, tS);
    }

    #pragma unroll
    for (int o = 16; o > 0; o >>= 1) {
        fs += __shfl_xor_sync(FULL, fs, o);
        bA += __shfl_xor_sync(FULL, bA, o);
        bD += __shfl_xor_sync(FULL, bD, o);
        iS += __shfl_xor_sync(FULL, iS, o);
        pS += __shfl_xor_sync(FULL, pS, o);
        tS += __shfl_xor_sync(FULL, tS, o);
        mx  = fmaxf(mx, __shfl_xor_sync(FULL, mx, o));
    }
    if (lane == 0) {
        red[w][0] = fs; red[w][1] = bA; red[w][2] = bD;
        red[w][3] = iS; red[w][4] = pS; red[w][5] = tS;
        atomicMax(&g_mxi[b], __float_as_int(mx));
    }
    __syncthreads();
    if (t == 0) {
        float a0=0,a1=0,a2=0,a3=0,a4=0,a5=0;
        #pragma unroll
        for (int ww = 0; ww < 4; ww++) {
            a0+=red[ww][0]; a1+=red[ww][1]; a2+=red[ww][2];
            a3+=red[ww][3]; a4+=red[ww][4]; a5+=red[ww][5];
        }
        atomicAdd(&g_acc[0], (double)a0);
        atomicAdd(&g_acc[1], (double)a1);
        atomicAdd(&g_acc[2 + b],        (double)a2);
        atomicAdd(&g_acc[2 + NB + b],   (double)a3);
        atomicAdd(&g_acc[2 + 2*NB + b], (double)a4);
        atomicAdd(&g_acc[2 + 3*NB + b], (double)a5);
    }
}

// ---------------------------------------------------------------------------
__global__ void k_final(const float* __restrict__ lv, float* __restrict__ out) {
    double N = (double)NB * (double)NPIX;
    double focal = g_acc[0] / N;
    double bndsum = g_acc[1];
    double ds = 0.0, us = 0.0;
    for (int b = 0; b < NB; b++) {
        double mx = (double)__int_as_float(g_mxi[b]);
        double dd = g_acc[2 + b];
        bndsum += (mx > 0.0) ? dd / mx : dd;
        double inter = g_acc[2 + NB + b];
        double tot   = g_acc[2 + 2*NB + b] + g_acc[2 + 3*NB + b];
        ds += (2.0*inter + 1e-6) / (tot + 1e-6);
        us += (inter + 1e-6) / (tot - inter + 1e-6);
    }
    double bnd  = bndsum / N;
    double dice = 1.0 - ds / NB;
    double iou  = 1.0 - us / NB;
    double l0 = lv[0], l1 = lv[1], l2 = lv[2], l3 = lv[3];
    double total = exp(-l0)*focal + l0 + exp(-l1)*dice + l1
                 + exp(-l2)*bnd + l2 + exp(-l3)*iou + l3;
    out[0] = (float)total;
    out[1] = (float)focal;
    out[2] = (float)dice;
    out[3] = (float)bnd;
    out[4] = (float)iou;
    for (int i = 0; i < 2 + 4*NB; i++) g_acc[i] = 0.0;
    for (int i = 0; i < NB; i++) g_mxi[i] = 0;
}

// ---------------------------------------------------------------------------
extern "C" void kernel_launch(void* const* d_in, const int* in_sizes, int n_in,
                              void* d_out, int out_size) {
    const float* pred = (const float*)d_in[0];
    const int*   tgt  = (const int*)d_in[1];
    const float* lv   = (const float*)d_in[2];
    float* out = (float*)d_out;

    kA1<<<dim3(MB, NB), 128>>>(tgt);
    k_conv<1><<<dim3(NPAIR, NB), 128>>>();
    kC1A2<<<dim3(MB, NB), 128>>>();
    k_conv<2><<<dim3(NPAIR, NB), 128>>>();
    kC2L<<<dim3(MB, NB), 128>>>(pred);
    k_final<<<1, 1>>>(lv, out);
}